// round 2
// baseline (speedup 1.0000x reference)
#include <cuda_runtime.h>
#include <cuda_bf16.h>
#include <math.h>

#define Nn   64
#define Tt   32
#define DA   1280
#define PP   16
#define WDIM 300
#define HH   512
#define H4   2048
#define VV   32000

__device__ float    g_Ap [Nn*PP*HH];
__device__ float    g_AW [Nn*PP*H4];
__device__ float    g_Whr[HH*H4];
__device__ float    g_xpr[(Nn*Tt)*H4];
__device__ float    g_h  [2][Nn*HH];
__device__ float    g_hn [(Nn*Tt)*HH];
__device__ unsigned g_bar;

// ---- K1: A_proj[r=n*16+p][h] = sum_c A[n][c][p]*conv_w[h][c] + conv_b[h] ----
__global__ void __launch_bounds__(256) k1_conv(const float* __restrict__ A,
                                               const float* __restrict__ Wc,
                                               const float* __restrict__ bc)
{
    __shared__ float As[16][68];
    __shared__ float Ws[16][68];
    int tid = threadIdx.x;
    int m0 = blockIdx.y * 64, h0 = blockIdx.x * 64;
    int tm = (tid >> 4) * 4, tn = (tid & 15) * 4;
    float acc[4][4] = {};
    int mL = tid & 63, kA = tid >> 6;
    int kW = tid & 15, hW = tid >> 4;
    int nA = (m0 + mL) >> 4, pA = (m0 + mL) & 15;
    const float* Abase = A + (long)nA * (DA * PP) + pA;
    for (int c0 = 0; c0 < DA; c0 += 16) {
#pragma unroll
        for (int it = 0; it < 4; it++) {
            int k = kA + it * 4;
            As[k][mL] = Abase[(c0 + k) * PP];
        }
#pragma unroll
        for (int it = 0; it < 4; it++) {
            int h = hW + it * 16;
            Ws[kW][h] = Wc[(long)(h0 + h) * DA + c0 + kW];
        }
        __syncthreads();
#pragma unroll
        for (int k = 0; k < 16; k++) {
            float4 a = *(const float4*)&As[k][tm];
            float4 b = *(const float4*)&Ws[k][tn];
            float av[4] = {a.x,a.y,a.z,a.w};
            float bv[4] = {b.x,b.y,b.z,b.w};
#pragma unroll
            for (int i = 0; i < 4; i++)
#pragma unroll
                for (int j = 0; j < 4; j++) acc[i][j] += av[i] * bv[j];
        }
        __syncthreads();
    }
#pragma unroll
    for (int i = 0; i < 4; i++) {
        int r = m0 + tm + i;
#pragma unroll
        for (int j = 0; j < 4; j++)
            g_Ap[(long)r * HH + h0 + tn + j] = acc[i][j] + bc[h0 + tn + j];
    }
}

// ---- h0 = mean over 16 spatial positions ----
__global__ void k1b_h0()
{
    int n = blockIdx.x, t = threadIdx.x;
    const float4* ap = (const float4*)(g_Ap + (long)n * PP * HH);
    float4 s = make_float4(0.f,0.f,0.f,0.f);
#pragma unroll
    for (int p = 0; p < PP; p++) {
        float4 v = ap[p * 128 + t];
        s.x += v.x; s.y += v.y; s.z += v.z; s.w += v.w;
    }
    s.x *= 0.0625f; s.y *= 0.0625f; s.z *= 0.0625f; s.w *= 0.0625f;
    ((float4*)(g_h[0] + (long)n * HH))[t] = s;
}

// ---- gate-interleave Wh: Whr4[k*512+h] = {Wh[k][h], Wh[k][h+512], ...} ----
__global__ void k_whr(const float* __restrict__ Wh)
{
    int idx = blockIdx.x * 256 + threadIdx.x;   // 0..262143
    int k = idx >> 9, h = idx & 511;
    const float* src = Wh + (long)k * H4 + h;
    ((float4*)g_Whr)[idx] = make_float4(src[0], src[512], src[1024], src[1536]);
}

// ---- generic 128x128 SGEMM body ----
template<bool GATHER, bool BIAS>
__device__ __forceinline__ void gemm128_body(
    const float* __restrict__ Amat, int lda, int Kd,
    const float* __restrict__ Bmat, int ldb,
    const float* __restrict__ bias,
    float* __restrict__ C, int ldc,
    const int* __restrict__ caps)
{
    __shared__ float As[16][132];
    __shared__ float Bs[16][128];
    int tid = threadIdx.x;
    int m0 = blockIdx.y * 128, c0 = blockIdx.x * 128;
    int tm = (tid >> 4) * 8, tn = (tid & 15) * 8;
    float acc[8][8] = {};
    int mA = tid >> 2, kq = (tid & 3) * 4;
    const float *arow0, *arow1;
    {
        int r0 = m0 + mA, r1 = r0 + 64;
        if (GATHER) {
            arow0 = Amat + (long)caps[(r0 & 63) * Tt + (r0 >> 6)] * lda;
            arow1 = Amat + (long)caps[(r1 & 63) * Tt + (r1 >> 6)] * lda;
        } else {
            arow0 = Amat + (long)r0 * lda;
            arow1 = Amat + (long)r1 * lda;
        }
    }
    int kB = tid >> 5, cB = (tid & 31) * 4;
    int nchunk = (Kd + 15) >> 4;
    for (int ch = 0; ch < nchunk; ch++) {
        int k0 = ch * 16;
        if (k0 + 16 <= Kd) {
            float4 a0 = *(const float4*)(arow0 + k0 + kq);
            float4 a1 = *(const float4*)(arow1 + k0 + kq);
            As[kq+0][mA] = a0.x; As[kq+1][mA] = a0.y;
            As[kq+2][mA] = a0.z; As[kq+3][mA] = a0.w;
            As[kq+0][mA+64] = a1.x; As[kq+1][mA+64] = a1.y;
            As[kq+2][mA+64] = a1.z; As[kq+3][mA+64] = a1.w;
        } else {
#pragma unroll
            for (int i = 0; i < 4; i++) {
                int k = k0 + kq + i;
                As[kq+i][mA]    = (k < Kd) ? arow0[k] : 0.f;
                As[kq+i][mA+64] = (k < Kd) ? arow1[k] : 0.f;
            }
        }
#pragma unroll
        for (int it = 0; it < 2; it++) {
            int k = k0 + kB + it * 8;
            float4 bv = (k < Kd) ? *(const float4*)(Bmat + (long)k * ldb + c0 + cB)
                                 : make_float4(0.f,0.f,0.f,0.f);
            *(float4*)&Bs[kB + it*8][cB] = bv;
        }
        __syncthreads();
#pragma unroll
        for (int k = 0; k < 16; k++) {
            float4 a0 = *(const float4*)&As[k][tm];
            float4 a1 = *(const float4*)&As[k][tm+4];
            float4 b0 = *(const float4*)&Bs[k][tn];
            float4 b1 = *(const float4*)&Bs[k][tn+4];
            float av[8] = {a0.x,a0.y,a0.z,a0.w,a1.x,a1.y,a1.z,a1.w};
            float bv[8] = {b0.x,b0.y,b0.z,b0.w,b1.x,b1.y,b1.z,b1.w};
#pragma unroll
            for (int i = 0; i < 8; i++)
#pragma unroll
                for (int j = 0; j < 8; j++) acc[i][j] += av[i] * bv[j];
        }
        __syncthreads();
    }
    float4 bia0 = make_float4(0,0,0,0), bia1 = bia0;
    if (BIAS) {
        bia0 = *(const float4*)(bias + c0 + tn);
        bia1 = *(const float4*)(bias + c0 + tn + 4);
    }
#pragma unroll
    for (int i = 0; i < 8; i++) {
        long r = m0 + tm + i;
        float4 o0 = make_float4(acc[i][0]+bia0.x, acc[i][1]+bia0.y,
                                acc[i][2]+bia0.z, acc[i][3]+bia0.w);
        float4 o1 = make_float4(acc[i][4]+bia1.x, acc[i][5]+bia1.y,
                                acc[i][6]+bia1.z, acc[i][7]+bia1.w);
        *(float4*)(C + r * ldc + c0 + tn)     = o0;
        *(float4*)(C + r * ldc + c0 + tn + 4) = o1;
    }
}

__global__ void __launch_bounds__(256, 2) k_gemm_aw(const float* __restrict__ Wattn)
{ gemm128_body<false,false>(g_Ap, HH, HH, Wattn, H4, nullptr, g_AW, H4, nullptr); }

__global__ void __launch_bounds__(256, 2) k_gemm_x(const float* __restrict__ Wemb,
                                                   const float* __restrict__ Wx,
                                                   const float* __restrict__ bb,
                                                   const int*   __restrict__ caps)
{ gemm128_body<true,true>(Wemb, WDIM, WDIM, Wx, H4, bb, g_xpr, H4, caps); }

__global__ void __launch_bounds__(256, 2) k_gemm_out(const float* __restrict__ Wv,
                                                     const float* __restrict__ bv,
                                                     float* __restrict__ out)
{ gemm128_body<false,true>(g_hn, HH, HH, Wv, VV, bv, out, VV, nullptr); }

__global__ void k_reset() { g_bar = 0u; }

// ---- persistent attention-LSTM, 128 CTAs x 256 thr, grid barrier per step ----
__global__ void __launch_bounds__(256) k3_lstm()
{
    __shared__ float h_s[8 * HH];
    __shared__ float sc[8][16];
    __shared__ float w_s[8][16];
    int tid = threadIdx.x;
    int blk = blockIdx.x;
    int ng = blk >> 4, hcg = blk & 15;
    int n0 = ng * 8;
    int n_l = tid >> 5, hc_l = tid & 31;
    int n = n0 + n_l;
    int hcol = hcg * 32 + hc_l;
    float c_reg = g_h[0][(long)n * HH + hcol];
    int pairn = tid >> 5, pairp = (tid >> 1) & 15, half = tid & 1;
    const float SCALE = 0.04419417382415922f;  // 1/sqrt(512)

    for (int t = 0; t < Tt; t++) {
        int cur = t & 1;
        const float4* hg = (const float4*)(g_h[cur] + (long)n0 * HH);
        float4* hs4 = (float4*)h_s;
#pragma unroll
        for (int q = 0; q < 4; q++)
            hs4[tid + q * 256] = __ldcg(&hg[tid + q * 256]);
        __syncthreads();

        // scores: 8n x 16p dots, 2 threads per dot
        {
            const float4* ap4 = (const float4*)(g_Ap + ((long)(n0+pairn)*PP + pairp)*HH) + half*64;
            const float4* hh4 = (const float4*)(h_s + pairn * HH) + half*64;
            float s = 0.f;
#pragma unroll 8
            for (int i = 0; i < 64; i++) {
                float4 a = __ldg(&ap4[i]);
                float4 h = hh4[i];
                s += a.x*h.x + a.y*h.y + a.z*h.z + a.w*h.w;
            }
            s += __shfl_xor_sync(0xffffffffu, s, 1);
            if (!half) sc[pairn][pairp] = s * SCALE;
        }
        __syncthreads();

        // softmax over 16 positions (warp w -> n_local w)
        {
            int w = tid >> 5, lane = tid & 31;
            float v = (lane < 16) ? sc[w][lane] : -3.0e38f;
            float mx = v;
#pragma unroll
            for (int o = 16; o; o >>= 1) mx = fmaxf(mx, __shfl_xor_sync(0xffffffffu, mx, o));
            float e = (lane < 16) ? __expf(v - mx) : 0.f;
            float sum = e;
#pragma unroll
            for (int o = 16; o; o >>= 1) sum += __shfl_xor_sync(0xffffffffu, sum, o);
            if (lane < 16) w_s[w][lane] = e / sum;
        }
        __syncthreads();

        // gates
        {
            long xb = ((long)(t * Nn + n)) * H4 + hcol;
            float a0 = __ldg(&g_xpr[xb]);
            float a1 = __ldg(&g_xpr[xb + 512]);
            float a2 = __ldg(&g_xpr[xb + 1024]);
            float a3 = __ldg(&g_xpr[xb + 1536]);
#pragma unroll
            for (int p = 0; p < PP; p++) {
                float wv = w_s[n_l][p];
                const float* awb = g_AW + ((long)(n * PP) + p) * H4 + hcol;
                a0 += wv * __ldg(awb);
                a1 += wv * __ldg(awb + 512);
                a2 += wv * __ldg(awb + 1024);
                a3 += wv * __ldg(awb + 1536);
            }
            const float4* wr = ((const float4*)g_Whr) + hcol;
            const float* hrow = h_s + n_l * HH;
#pragma unroll 8
            for (int k = 0; k < HH; k++) {
                float hv = hrow[k];
                float4 w4 = __ldg(wr); wr += HH;
                a0 += hv * w4.x; a1 += hv * w4.y;
                a2 += hv * w4.z; a3 += hv * w4.w;
            }
            float ii = 1.f / (1.f + __expf(-a0));
            float ff = 1.f / (1.f + __expf(-a1));
            float oo = 1.f / (1.f + __expf(-a2));
            float gg = tanhf(a3);
            c_reg = ff * c_reg + ii * gg;
            float hnv = oo * tanhf(c_reg);
            __stcg(&g_h[cur ^ 1][(long)n * HH + hcol], hnv);
            __stcg(&g_hn[((long)n * Tt + t) * HH + hcol], hnv);
        }
        __syncthreads();

        // software grid barrier (128 co-resident CTAs)
        __threadfence();
        if (tid == 0) {
            atomicAdd(&g_bar, 1u);
            unsigned target = (unsigned)(t + 1) * 128u;
            while (atomicAdd(&g_bar, 0u) < target) { }
        }
        __syncthreads();
    }
}

extern "C" void kernel_launch(void* const* d_in, const int* in_sizes, int n_in,
                              void* d_out, int out_size)
{
    const float* A      = (const float*)d_in[0];
    const int*   caps   = (const int*)  d_in[1];
    const float* conv_w = (const float*)d_in[2];
    const float* conv_b = (const float*)d_in[3];
    const float* Wx     = (const float*)d_in[4];
    const float* Wh     = (const float*)d_in[5];
    const float* Wattn  = (const float*)d_in[6];
    const float* b      = (const float*)d_in[7];
    const float* Wemb   = (const float*)d_in[8];
    const float* Wv     = (const float*)d_in[9];
    const float* bv     = (const float*)d_in[10];
    float* out = (float*)d_out;

    k1_conv<<<dim3(8, 16), 256>>>(A, conv_w, conv_b);
    k1b_h0<<<64, 128>>>();
    k_whr<<<1024, 256>>>(Wh);
    k_gemm_aw<<<dim3(16, 8), 256>>>(Wattn);
    k_gemm_x<<<dim3(16, 16), 256>>>(Wemb, Wx, b, caps);
    k_reset<<<1, 1>>>();
    k3_lstm<<<128, 256>>>();
    k_gemm_out<<<dim3(250, 16), 256>>>(Wv, bv, out);
}

// round 4
// speedup vs baseline: 1.3678x; 1.3678x over previous
#include <cuda_runtime.h>
#include <cuda_bf16.h>
#include <cuda_fp16.h>
#include <math.h>
#include <cstdint>

#define Nn   64
#define Tt   32
#define DA   1280
#define PP   16
#define WDIM 300
#define HH   512
#define H4   2048
#define VV   32000

__device__ float    g_Ap [Nn*PP*HH];
__device__ float    g_AW [Nn*PP*H4];
__device__ float    g_Whr[HH*H4];
__device__ float    g_xpr[(Nn*Tt)*H4];
__device__ float    g_h  [2][Nn*HH];
__device__ float    g_hn [(Nn*Tt)*HH];
__device__ unsigned g_bar;
__device__ __half   g_hnH[(Nn*Tt)*HH];
__device__ __half   g_hnL[(Nn*Tt)*HH];
__device__ __half   g_WvH[(size_t)VV*HH];
__device__ __half   g_WvL[(size_t)VV*HH];

// ---- K1: A_proj[r=n*16+p][h] = sum_c A[n][c][p]*conv_w[h][c] + conv_b[h] ----
__global__ void __launch_bounds__(256) k1_conv(const float* __restrict__ A,
                                               const float* __restrict__ Wc,
                                               const float* __restrict__ bc)
{
    __shared__ float As[16][68];
    __shared__ float Ws[16][68];
    int tid = threadIdx.x;
    int m0 = blockIdx.y * 64, h0 = blockIdx.x * 64;
    int tm = (tid >> 4) * 4, tn = (tid & 15) * 4;
    float acc[4][4] = {};
    int mL = tid & 63, kA = tid >> 6;
    int kW = tid & 15, hW = tid >> 4;
    int nA = (m0 + mL) >> 4, pA = (m0 + mL) & 15;
    const float* Abase = A + (long)nA * (DA * PP) + pA;
    for (int c0 = 0; c0 < DA; c0 += 16) {
#pragma unroll
        for (int it = 0; it < 4; it++) {
            int k = kA + it * 4;
            As[k][mL] = Abase[(c0 + k) * PP];
        }
#pragma unroll
        for (int it = 0; it < 4; it++) {
            int h = hW + it * 16;
            Ws[kW][h] = Wc[(long)(h0 + h) * DA + c0 + kW];
        }
        __syncthreads();
#pragma unroll
        for (int k = 0; k < 16; k++) {
            float4 a = *(const float4*)&As[k][tm];
            float4 b = *(const float4*)&Ws[k][tn];
            float av[4] = {a.x,a.y,a.z,a.w};
            float bv[4] = {b.x,b.y,b.z,b.w};
#pragma unroll
            for (int i = 0; i < 4; i++)
#pragma unroll
                for (int j = 0; j < 4; j++) acc[i][j] += av[i] * bv[j];
        }
        __syncthreads();
    }
#pragma unroll
    for (int i = 0; i < 4; i++) {
        int r = m0 + tm + i;
#pragma unroll
        for (int j = 0; j < 4; j++)
            g_Ap[(long)r * HH + h0 + tn + j] = acc[i][j] + bc[h0 + tn + j];
    }
}

// ---- h0 = mean over 16 spatial positions ----
__global__ void k1b_h0()
{
    int n = blockIdx.x, t = threadIdx.x;
    const float4* ap = (const float4*)(g_Ap + (long)n * PP * HH);
    float4 s = make_float4(0.f,0.f,0.f,0.f);
#pragma unroll
    for (int p = 0; p < PP; p++) {
        float4 v = ap[p * 128 + t];
        s.x += v.x; s.y += v.y; s.z += v.z; s.w += v.w;
    }
    s.x *= 0.0625f; s.y *= 0.0625f; s.z *= 0.0625f; s.w *= 0.0625f;
    ((float4*)(g_h[0] + (long)n * HH))[t] = s;
}

// ---- gate-interleave Wh ----
__global__ void k_whr(const float* __restrict__ Wh)
{
    int idx = blockIdx.x * 256 + threadIdx.x;
    int k = idx >> 9, h = idx & 511;
    const float* src = Wh + (long)k * H4 + h;
    ((float4*)g_Whr)[idx] = make_float4(src[0], src[512], src[1024], src[1536]);
}

// ---- generic 128x128 SGEMM body (AW and X pre-GEMMs) ----
template<bool GATHER, bool BIAS>
__device__ __forceinline__ void gemm128_body(
    const float* __restrict__ Amat, int lda, int Kd,
    const float* __restrict__ Bmat, int ldb,
    const float* __restrict__ bias,
    float* __restrict__ C, int ldc,
    const int* __restrict__ caps)
{
    __shared__ float As[16][132];
    __shared__ float Bs[16][128];
    int tid = threadIdx.x;
    int m0 = blockIdx.y * 128, c0 = blockIdx.x * 128;
    int tm = (tid >> 4) * 8, tn = (tid & 15) * 8;
    float acc[8][8] = {};
    int mA = tid >> 2, kq = (tid & 3) * 4;
    const float *arow0, *arow1;
    {
        int r0 = m0 + mA, r1 = r0 + 64;
        if (GATHER) {
            arow0 = Amat + (long)caps[(r0 & 63) * Tt + (r0 >> 6)] * lda;
            arow1 = Amat + (long)caps[(r1 & 63) * Tt + (r1 >> 6)] * lda;
        } else {
            arow0 = Amat + (long)r0 * lda;
            arow1 = Amat + (long)r1 * lda;
        }
    }
    int kB = tid >> 5, cB = (tid & 31) * 4;
    int nchunk = (Kd + 15) >> 4;
    for (int ch = 0; ch < nchunk; ch++) {
        int k0 = ch * 16;
        if (k0 + 16 <= Kd) {
            float4 a0 = *(const float4*)(arow0 + k0 + kq);
            float4 a1 = *(const float4*)(arow1 + k0 + kq);
            As[kq+0][mA] = a0.x; As[kq+1][mA] = a0.y;
            As[kq+2][mA] = a0.z; As[kq+3][mA] = a0.w;
            As[kq+0][mA+64] = a1.x; As[kq+1][mA+64] = a1.y;
            As[kq+2][mA+64] = a1.z; As[kq+3][mA+64] = a1.w;
        } else {
#pragma unroll
            for (int i = 0; i < 4; i++) {
                int k = k0 + kq + i;
                As[kq+i][mA]    = (k < Kd) ? arow0[k] : 0.f;
                As[kq+i][mA+64] = (k < Kd) ? arow1[k] : 0.f;
            }
        }
#pragma unroll
        for (int it = 0; it < 2; it++) {
            int k = k0 + kB + it * 8;
            float4 bv = (k < Kd) ? *(const float4*)(Bmat + (long)k * ldb + c0 + cB)
                                 : make_float4(0.f,0.f,0.f,0.f);
            *(float4*)&Bs[kB + it*8][cB] = bv;
        }
        __syncthreads();
#pragma unroll
        for (int k = 0; k < 16; k++) {
            float4 a0 = *(const float4*)&As[k][tm];
            float4 a1 = *(const float4*)&As[k][tm+4];
            float4 b0 = *(const float4*)&Bs[k][tn];
            float4 b1 = *(const float4*)&Bs[k][tn+4];
            float av[8] = {a0.x,a0.y,a0.z,a0.w,a1.x,a1.y,a1.z,a1.w};
            float bv[8] = {b0.x,b0.y,b0.z,b0.w,b1.x,b1.y,b1.z,b1.w};
#pragma unroll
            for (int i = 0; i < 8; i++)
#pragma unroll
                for (int j = 0; j < 8; j++) acc[i][j] += av[i] * bv[j];
        }
        __syncthreads();
    }
    float4 bia0 = make_float4(0,0,0,0), bia1 = bia0;
    if (BIAS) {
        bia0 = *(const float4*)(bias + c0 + tn);
        bia1 = *(const float4*)(bias + c0 + tn + 4);
    }
#pragma unroll
    for (int i = 0; i < 8; i++) {
        long r = m0 + tm + i;
        float4 o0 = make_float4(acc[i][0]+bia0.x, acc[i][1]+bia0.y,
                                acc[i][2]+bia0.z, acc[i][3]+bia0.w);
        float4 o1 = make_float4(acc[i][4]+bia1.x, acc[i][5]+bia1.y,
                                acc[i][6]+bia1.z, acc[i][7]+bia1.w);
        *(float4*)(C + r * ldc + c0 + tn)     = o0;
        *(float4*)(C + r * ldc + c0 + tn + 4) = o1;
    }
}

__global__ void __launch_bounds__(256, 2) k_gemm_aw(const float* __restrict__ Wattn)
{ gemm128_body<false,false>(g_Ap, HH, HH, Wattn, H4, nullptr, g_AW, H4, nullptr); }

__global__ void __launch_bounds__(256, 2) k_gemm_x(const float* __restrict__ Wemb,
                                                   const float* __restrict__ Wx,
                                                   const float* __restrict__ bb,
                                                   const int*   __restrict__ caps)
{ gemm128_body<true,true>(Wemb, WDIM, WDIM, Wx, H4, bb, g_xpr, H4, caps); }

__global__ void k_reset() { g_bar = 0u; }

// ---- persistent attention-LSTM ----
__global__ void __launch_bounds__(256) k3_lstm()
{
    __shared__ float h_s[8 * HH];
    __shared__ float sc[8][16];
    __shared__ float w_s[8][16];
    int tid = threadIdx.x;
    int blk = blockIdx.x;
    int ng = blk >> 4, hcg = blk & 15;
    int n0 = ng * 8;
    int n_l = tid >> 5, hc_l = tid & 31;
    int n = n0 + n_l;
    int hcol = hcg * 32 + hc_l;
    float c_reg = g_h[0][(long)n * HH + hcol];
    int pairn = tid >> 5, pairp = (tid >> 1) & 15, half = tid & 1;
    const float SCALE = 0.04419417382415922f;

    for (int t = 0; t < Tt; t++) {
        int cur = t & 1;
        const float4* hg = (const float4*)(g_h[cur] + (long)n0 * HH);
        float4* hs4 = (float4*)h_s;
#pragma unroll
        for (int q = 0; q < 4; q++)
            hs4[tid + q * 256] = __ldcg(&hg[tid + q * 256]);
        __syncthreads();
        {
            const float4* ap4 = (const float4*)(g_Ap + ((long)(n0+pairn)*PP + pairp)*HH) + half*64;
            const float4* hh4 = (const float4*)(h_s + pairn * HH) + half*64;
            float s = 0.f;
#pragma unroll 8
            for (int i = 0; i < 64; i++) {
                float4 a = __ldg(&ap4[i]);
                float4 h = hh4[i];
                s += a.x*h.x + a.y*h.y + a.z*h.z + a.w*h.w;
            }
            s += __shfl_xor_sync(0xffffffffu, s, 1);
            if (!half) sc[pairn][pairp] = s * SCALE;
        }
        __syncthreads();
        {
            int w = tid >> 5, lane = tid & 31;
            float v = (lane < 16) ? sc[w][lane] : -3.0e38f;
            float mx = v;
#pragma unroll
            for (int o = 16; o; o >>= 1) mx = fmaxf(mx, __shfl_xor_sync(0xffffffffu, mx, o));
            float e = (lane < 16) ? __expf(v - mx) : 0.f;
            float sum = e;
#pragma unroll
            for (int o = 16; o; o >>= 1) sum += __shfl_xor_sync(0xffffffffu, sum, o);
            if (lane < 16) w_s[w][lane] = e / sum;
        }
        __syncthreads();
        {
            long xb = ((long)(t * Nn + n)) * H4 + hcol;
            float a0 = __ldg(&g_xpr[xb]);
            float a1 = __ldg(&g_xpr[xb + 512]);
            float a2 = __ldg(&g_xpr[xb + 1024]);
            float a3 = __ldg(&g_xpr[xb + 1536]);
#pragma unroll
            for (int p = 0; p < PP; p++) {
                float wv = w_s[n_l][p];
                const float* awb = g_AW + ((long)(n * PP) + p) * H4 + hcol;
                a0 += wv * __ldg(awb);
                a1 += wv * __ldg(awb + 512);
                a2 += wv * __ldg(awb + 1024);
                a3 += wv * __ldg(awb + 1536);
            }
            const float4* wr = ((const float4*)g_Whr) + hcol;
            const float* hrow = h_s + n_l * HH;
#pragma unroll 8
            for (int k = 0; k < HH; k++) {
                float hv = hrow[k];
                float4 w4 = __ldg(wr); wr += HH;
                a0 += hv * w4.x; a1 += hv * w4.y;
                a2 += hv * w4.z; a3 += hv * w4.w;
            }
            float ii = 1.f / (1.f + __expf(-a0));
            float ff = 1.f / (1.f + __expf(-a1));
            float oo = 1.f / (1.f + __expf(-a2));
            float gg = tanhf(a3);
            c_reg = ff * c_reg + ii * gg;
            float hnv = oo * tanhf(c_reg);
            __stcg(&g_h[cur ^ 1][(long)n * HH + hcol], hnv);
            __stcg(&g_hn[((long)n * Tt + t) * HH + hcol], hnv);
        }
        __syncthreads();
        __threadfence();
        if (tid == 0) {
            atomicAdd(&g_bar, 1u);
            unsigned target = (unsigned)(t + 1) * 128u;
            while (atomicAdd(&g_bar, 0u) < target) { }
        }
        __syncthreads();
    }
}

// ---- split hn into fp16 hi/lo planes ----
__global__ void k_split_hn()
{
    int i = blockIdx.x * 256 + threadIdx.x;
    float v = g_hn[i];
    __half h = __float2half_rn(v);
    g_hnH[i] = h;
    g_hnL[i] = __float2half_rn(v - __half2float(h));
}

// ---- transpose + split W_vocab: [k][n] f32 -> [n][k] half hi/lo ----
__global__ void __launch_bounds__(256) k_trans_wv(const float* __restrict__ Wv)
{
    __shared__ float t[32][33];
    int n0 = blockIdx.x * 32, k0 = blockIdx.y * 32;
    int tx = threadIdx.x & 31, ty = threadIdx.x >> 5;
#pragma unroll
    for (int j = 0; j < 4; j++)
        t[ty + 8*j][tx] = Wv[(size_t)(k0 + ty + 8*j) * VV + n0 + tx];
    __syncthreads();
#pragma unroll
    for (int j = 0; j < 4; j++) {
        int n = n0 + ty + 8*j, k = k0 + tx;
        float v = t[tx][ty + 8*j];
        __half h = __float2half_rn(v);
        g_WvH[(size_t)n * HH + k] = h;
        g_WvL[(size_t)n * HH + k] = __float2half_rn(v - __half2float(h));
    }
}

// ================= fp16-split HMMA vocab GEMM =================
// out[2048 x 32000] = hn @ Wv + bv, computed as ah*bh + ah*bl + al*bh
#define VS_SMEM (3 * 32768)

__device__ __forceinline__ uint32_t s2u(const void* p) {
    uint32_t a;
    asm("{ .reg .u64 t; cvta.to.shared.u64 t, %1; cvt.u32.u64 %0, t; }" : "=r"(a) : "l"(p));
    return a;
}

#define CPA(dst, src) asm volatile("cp.async.cg.shared.global [%0], [%1], 16;" \
    :: "r"(dst), "l"(src) : "memory")
#define LDSM4(r, addr) asm volatile( \
    "ldmatrix.sync.aligned.m8n8.x4.shared.b16 {%0,%1,%2,%3}, [%4];" \
    : "=r"((r)[0]),"=r"((r)[1]),"=r"((r)[2]),"=r"((r)[3]) : "r"(addr))
#define MMA16816(c, a, b0, b1) asm volatile( \
    "mma.sync.aligned.m16n8k16.row.col.f32.f16.f16.f32 " \
    "{%0,%1,%2,%3}, {%4,%5,%6,%7}, {%8,%9}, {%0,%1,%2,%3};" \
    : "+f"((c)[0]), "+f"((c)[1]), "+f"((c)[2]), "+f"((c)[3]) \
    : "r"((a)[0]),"r"((a)[1]),"r"((a)[2]),"r"((a)[3]), "r"(b0),"r"(b1))

__global__ void __launch_bounds__(256) k_vocab_mma(const float* __restrict__ bv,
                                                   float* __restrict__ out)
{
    extern __shared__ char sm[];
    const uint32_t sbase = s2u(sm);
    const int tid = threadIdx.x;
    const int lane = tid & 31, w = tid >> 5;
    const int m0 = blockIdx.x * 128, n0 = blockIdx.y * 128;
    const int wm = (w & 1) * 64, wn = (w >> 1) * 32;

    float acc[4][4][4];
#pragma unroll
    for (int i = 0; i < 4; i++)
#pragma unroll
        for (int j = 0; j < 4; j++)
#pragma unroll
            for (int q = 0; q < 4; q++) acc[i][j][q] = 0.f;

    // cp.async source/dest mapping: thread handles row r, granule kk per plane/sub
    const int r = tid >> 1, kk = tid & 1;
    const uint32_t swo = (uint32_t)(r * 32 + ((kk ^ ((r >> 2) & 1)) << 4));
    const __half* gAH = g_hnH + (size_t)(m0 + r) * HH + kk * 8;
    const __half* gAL = g_hnL + (size_t)(m0 + r) * HH + kk * 8;
    const __half* gBH = g_WvH + (size_t)(n0 + r) * HH + kk * 8;
    const __half* gBL = g_WvL + (size_t)(n0 + r) * HH + kk * 8;

    // ldmatrix offsets
    uint32_t aoff[4], boff[2];
#pragma unroll
    for (int mt = 0; mt < 4; mt++) {
        int ml = wm + mt * 16 + (lane & 15);
        int kl = lane >> 4;
        aoff[mt] = (uint32_t)(ml * 32 + ((kl ^ ((ml >> 2) & 1)) << 4));
    }
#pragma unroll
    for (int q = 0; q < 2; q++) {
        int g = lane >> 3;
        int nl = wn + q * 16 + ((g >> 1) * 8) + (lane & 7);
        int kl = g & 1;
        boff[q] = (uint32_t)(nl * 32 + ((kl ^ ((nl >> 2) & 1)) << 4));
    }

#define VS_ISSUE(ks) do {                                                     \
    uint32_t st = sbase + (uint32_t)((ks) % 3) * 32768u;                      \
    int kof = (ks) * 32;                                                      \
    CPA(st +     0 + swo, gAH + kof);  CPA(st +  4096 + swo, gAH + kof + 16); \
    CPA(st +  8192 + swo, gAL + kof);  CPA(st + 12288 + swo, gAL + kof + 16); \
    CPA(st + 16384 + swo, gBH + kof);  CPA(st + 20480 + swo, gBH + kof + 16); \
    CPA(st + 24576 + swo, gBL + kof);  CPA(st + 28672 + swo, gBL + kof + 16); \
    asm volatile("cp.async.commit_group;" ::: "memory");                      \
} while (0)

    VS_ISSUE(0); VS_ISSUE(1); VS_ISSUE(2);

    for (int ks = 0; ks < 16; ks++) {
        asm volatile("cp.async.wait_group 2;" ::: "memory");
        __syncthreads();
        uint32_t stb = sbase + (uint32_t)(ks % 3) * 32768u;
#pragma unroll
        for (int s = 0; s < 2; s++) {
            uint32_t sub = stb + (uint32_t)s * 4096u;
            uint32_t aH[4][4], aL[4][4], bH[2][4], bL[2][4];
#pragma unroll
            for (int mt = 0; mt < 4; mt++) {
                LDSM4(aH[mt], sub + aoff[mt]);
                LDSM4(aL[mt], sub + 8192 + aoff[mt]);
            }
#pragma unroll
            for (int q = 0; q < 2; q++) {
                LDSM4(bH[q], sub + 16384 + boff[q]);
                LDSM4(bL[q], sub + 24576 + boff[q]);
            }
#pragma unroll
            for (int mt = 0; mt < 4; mt++)
#pragma unroll
                for (int nt = 0; nt < 4; nt++) {
                    uint32_t b0h = bH[nt >> 1][(nt & 1) * 2];
                    uint32_t b1h = bH[nt >> 1][(nt & 1) * 2 + 1];
                    uint32_t b0l = bL[nt >> 1][(nt & 1) * 2];
                    uint32_t b1l = bL[nt >> 1][(nt & 1) * 2 + 1];
                    MMA16816(acc[mt][nt], aH[mt], b0h, b1h);
                    MMA16816(acc[mt][nt], aH[mt], b0l, b1l);
                    MMA16816(acc[mt][nt], aL[mt], b0h, b1h);
                }
        }
        __syncthreads();
        if (ks + 3 < 16) VS_ISSUE(ks + 3);
    }

    // epilogue
#pragma unroll
    for (int mt = 0; mt < 4; mt++)
#pragma unroll
        for (int nt = 0; nt < 4; nt++) {
            int mrow = m0 + wm + mt * 16 + (lane >> 2);
            int ncol = n0 + wn + nt * 8 + 2 * (lane & 3);
            float b0 = __ldg(bv + ncol), b1 = __ldg(bv + ncol + 1);
            float2 v0 = make_float2(acc[mt][nt][0] + b0, acc[mt][nt][1] + b1);
            float2 v1 = make_float2(acc[mt][nt][2] + b0, acc[mt][nt][3] + b1);
            *(float2*)(out + (size_t)mrow * VV + ncol)       = v0;
            *(float2*)(out + (size_t)(mrow + 8) * VV + ncol) = v1;
        }
}

extern "C" void kernel_launch(void* const* d_in, const int* in_sizes, int n_in,
                              void* d_out, int out_size)
{
    const float* A      = (const float*)d_in[0];
    const int*   caps   = (const int*)  d_in[1];
    const float* conv_w = (const float*)d_in[2];
    const float* conv_b = (const float*)d_in[3];
    const float* Wx     = (const float*)d_in[4];
    const float* Wh     = (const float*)d_in[5];
    const float* Wattn  = (const float*)d_in[6];
    const float* b      = (const float*)d_in[7];
    const float* Wemb   = (const float*)d_in[8];
    const float* Wv     = (const float*)d_in[9];
    const float* bv     = (const float*)d_in[10];
    float* out = (float*)d_out;

    cudaFuncSetAttribute(k_vocab_mma, cudaFuncAttributeMaxDynamicSharedMemorySize, VS_SMEM);

    k_trans_wv<<<dim3(1000, 16), 256>>>(Wv);
    k1_conv<<<dim3(8, 16), 256>>>(A, conv_w, conv_b);
    k1b_h0<<<64, 128>>>();
    k_whr<<<1024, 256>>>(Wh);
    k_gemm_aw<<<dim3(16, 8), 256>>>(Wattn);
    k_gemm_x<<<dim3(16, 16), 256>>>(Wemb, Wx, b, caps);
    k_reset<<<1, 1>>>();
    k3_lstm<<<128, 256>>>();
    k_split_hn<<<4096, 256>>>();
    k_vocab_mma<<<dim3(16, 250), 256, VS_SMEM>>>(bv, out);
}

// round 5
// speedup vs baseline: 2.6500x; 1.9375x over previous
#include <cuda_runtime.h>
#include <cuda_bf16.h>
#include <cuda_fp16.h>
#include <math.h>
#include <cstdint>

#define Nn   64
#define Tt   32
#define DA   1280
#define PP   16
#define WDIM 300
#define HH   512
#define H4   2048
#define VV   32000

__device__ float    g_Ap [Nn*PP*HH];
__device__ float    g_AW [Nn*PP*H4];
__device__ float    g_Whr[HH*H4];
__device__ float    g_xpr[(Nn*Tt)*H4];
__device__ float    g_h  [2][Nn*HH];
__device__ float    g_hn [(Nn*Tt)*HH];
__device__ float    g_scp[2][32][Nn][PP];
__device__ unsigned g_bar;
__device__ __half   g_hnH[(Nn*Tt)*HH];
__device__ __half   g_hnL[(Nn*Tt)*HH];
__device__ __half   g_WvH[(size_t)VV*HH];
__device__ __half   g_WvL[(size_t)VV*HH];

// ---- K1: A_proj[r=n*16+p][h] = sum_c A[n][c][p]*conv_w[h][c] + conv_b[h] ----
__global__ void __launch_bounds__(256) k1_conv(const float* __restrict__ A,
                                               const float* __restrict__ Wc,
                                               const float* __restrict__ bc)
{
    __shared__ float As[16][68];
    __shared__ float Ws[16][68];
    int tid = threadIdx.x;
    int m0 = blockIdx.y * 64, h0 = blockIdx.x * 64;
    int tm = (tid >> 4) * 4, tn = (tid & 15) * 4;
    float acc[4][4] = {};
    int mL = tid & 63, kA = tid >> 6;
    int kW = tid & 15, hW = tid >> 4;
    int nA = (m0 + mL) >> 4, pA = (m0 + mL) & 15;
    const float* Abase = A + (long)nA * (DA * PP) + pA;
    for (int c0 = 0; c0 < DA; c0 += 16) {
#pragma unroll
        for (int it = 0; it < 4; it++) {
            int k = kA + it * 4;
            As[k][mL] = Abase[(c0 + k) * PP];
        }
#pragma unroll
        for (int it = 0; it < 4; it++) {
            int h = hW + it * 16;
            Ws[kW][h] = Wc[(long)(h0 + h) * DA + c0 + kW];
        }
        __syncthreads();
#pragma unroll
        for (int k = 0; k < 16; k++) {
            float4 a = *(const float4*)&As[k][tm];
            float4 b = *(const float4*)&Ws[k][tn];
            float av[4] = {a.x,a.y,a.z,a.w};
            float bv[4] = {b.x,b.y,b.z,b.w};
#pragma unroll
            for (int i = 0; i < 4; i++)
#pragma unroll
                for (int j = 0; j < 4; j++) acc[i][j] += av[i] * bv[j];
        }
        __syncthreads();
    }
#pragma unroll
    for (int i = 0; i < 4; i++) {
        int r = m0 + tm + i;
#pragma unroll
        for (int j = 0; j < 4; j++)
            g_Ap[(long)r * HH + h0 + tn + j] = acc[i][j] + bc[h0 + tn + j];
    }
}

// ---- h0 = mean over 16 spatial positions ----
__global__ void k1b_h0()
{
    int n = blockIdx.x, t = threadIdx.x;
    const float4* ap = (const float4*)(g_Ap + (long)n * PP * HH);
    float4 s = make_float4(0.f,0.f,0.f,0.f);
#pragma unroll
    for (int p = 0; p < PP; p++) {
        float4 v = ap[p * 128 + t];
        s.x += v.x; s.y += v.y; s.z += v.z; s.w += v.w;
    }
    s.x *= 0.0625f; s.y *= 0.0625f; s.z *= 0.0625f; s.w *= 0.0625f;
    ((float4*)(g_h[0] + (long)n * HH))[t] = s;
}

// ---- gate-interleave Wh ----
__global__ void k_whr(const float* __restrict__ Wh)
{
    int idx = blockIdx.x * 256 + threadIdx.x;
    int k = idx >> 9, h = idx & 511;
    const float* src = Wh + (long)k * H4 + h;
    ((float4*)g_Whr)[idx] = make_float4(src[0], src[512], src[1024], src[1536]);
}

// ---- generic 128x128 SGEMM body (AW and X pre-GEMMs) ----
template<bool GATHER, bool BIAS>
__device__ __forceinline__ void gemm128_body(
    const float* __restrict__ Amat, int lda, int Kd,
    const float* __restrict__ Bmat, int ldb,
    const float* __restrict__ bias,
    float* __restrict__ C, int ldc,
    const int* __restrict__ caps)
{
    __shared__ float As[16][132];
    __shared__ float Bs[16][128];
    int tid = threadIdx.x;
    int m0 = blockIdx.y * 128, c0 = blockIdx.x * 128;
    int tm = (tid >> 4) * 8, tn = (tid & 15) * 8;
    float acc[8][8] = {};
    int mA = tid >> 2, kq = (tid & 3) * 4;
    const float *arow0, *arow1;
    {
        int r0 = m0 + mA, r1 = r0 + 64;
        if (GATHER) {
            arow0 = Amat + (long)caps[(r0 & 63) * Tt + (r0 >> 6)] * lda;
            arow1 = Amat + (long)caps[(r1 & 63) * Tt + (r1 >> 6)] * lda;
        } else {
            arow0 = Amat + (long)r0 * lda;
            arow1 = Amat + (long)r1 * lda;
        }
    }
    int kB = tid >> 5, cB = (tid & 31) * 4;
    int nchunk = (Kd + 15) >> 4;
    for (int ch = 0; ch < nchunk; ch++) {
        int k0 = ch * 16;
        if (k0 + 16 <= Kd) {
            float4 a0 = *(const float4*)(arow0 + k0 + kq);
            float4 a1 = *(const float4*)(arow1 + k0 + kq);
            As[kq+0][mA] = a0.x; As[kq+1][mA] = a0.y;
            As[kq+2][mA] = a0.z; As[kq+3][mA] = a0.w;
            As[kq+0][mA+64] = a1.x; As[kq+1][mA+64] = a1.y;
            As[kq+2][mA+64] = a1.z; As[kq+3][mA+64] = a1.w;
        } else {
#pragma unroll
            for (int i = 0; i < 4; i++) {
                int k = k0 + kq + i;
                As[kq+i][mA]    = (k < Kd) ? arow0[k] : 0.f;
                As[kq+i][mA+64] = (k < Kd) ? arow1[k] : 0.f;
            }
        }
#pragma unroll
        for (int it = 0; it < 2; it++) {
            int k = k0 + kB + it * 8;
            float4 bv = (k < Kd) ? *(const float4*)(Bmat + (long)k * ldb + c0 + cB)
                                 : make_float4(0.f,0.f,0.f,0.f);
            *(float4*)&Bs[kB + it*8][cB] = bv;
        }
        __syncthreads();
#pragma unroll
        for (int k = 0; k < 16; k++) {
            float4 a0 = *(const float4*)&As[k][tm];
            float4 a1 = *(const float4*)&As[k][tm+4];
            float4 b0 = *(const float4*)&Bs[k][tn];
            float4 b1 = *(const float4*)&Bs[k][tn+4];
            float av[8] = {a0.x,a0.y,a0.z,a0.w,a1.x,a1.y,a1.z,a1.w};
            float bv[8] = {b0.x,b0.y,b0.z,b0.w,b1.x,b1.y,b1.z,b1.w};
#pragma unroll
            for (int i = 0; i < 8; i++)
#pragma unroll
                for (int j = 0; j < 8; j++) acc[i][j] += av[i] * bv[j];
        }
        __syncthreads();
    }
    float4 bia0 = make_float4(0,0,0,0), bia1 = bia0;
    if (BIAS) {
        bia0 = *(const float4*)(bias + c0 + tn);
        bia1 = *(const float4*)(bias + c0 + tn + 4);
    }
#pragma unroll
    for (int i = 0; i < 8; i++) {
        long r = m0 + tm + i;
        float4 o0 = make_float4(acc[i][0]+bia0.x, acc[i][1]+bia0.y,
                                acc[i][2]+bia0.z, acc[i][3]+bia0.w);
        float4 o1 = make_float4(acc[i][4]+bia1.x, acc[i][5]+bia1.y,
                                acc[i][6]+bia1.z, acc[i][7]+bia1.w);
        *(float4*)(C + r * ldc + c0 + tn)     = o0;
        *(float4*)(C + r * ldc + c0 + tn + 4) = o1;
    }
}

__global__ void __launch_bounds__(256, 2) k_gemm_aw(const float* __restrict__ Wattn)
{ gemm128_body<false,false>(g_Ap, HH, HH, Wattn, H4, nullptr, g_AW, H4, nullptr); }

__global__ void __launch_bounds__(256, 2) k_gemm_x(const float* __restrict__ Wemb,
                                                   const float* __restrict__ Wx,
                                                   const float* __restrict__ bb,
                                                   const int*   __restrict__ caps)
{ gemm128_body<true,true>(Wemb, WDIM, WDIM, Wx, H4, bb, g_xpr, H4, caps); }

__global__ void k_reset() { g_bar = 0u; }

// ================= persistent attention-LSTM (SMEM-resident Wh) =================
// 128 CTAs: ng = blk>>5 (16 n each), hcg = blk&31 (16 hcol each). 256 threads:
// thread (n_l = tid>>4, hc_l = tid&15) owns cell state c[n][hcol].
#define LS_SMEM 166912

__device__ __forceinline__ void gridbar(int tid, unsigned target)
{
    __threadfence();
    __syncthreads();
    if (tid == 0) {
        atomicAdd(&g_bar, 1u);
        while (*(volatile unsigned*)&g_bar < target) { }
    }
    __syncthreads();
}

__global__ void __launch_bounds__(256) k3_lstm()
{
    extern __shared__ char sm[];
    float4* Whs4 = (float4*)sm;                    // [512][16] float4 = 128KB
    float*  h_s  = (float*)(sm + 131072);          // [16][512]        = 32KB
    float*  sc_s = (float*)(sm + 163840);          // [16][16]
    float*  w_s  = (float*)(sm + 164864);          // [16][16]
    float*  hn_s = (float*)(sm + 165888);          // [16][16]

    const int tid = threadIdx.x, blk = blockIdx.x;
    const int ng = blk >> 5, hcg = blk & 31;
    const int n0 = ng * 16;
    const int n_l = tid >> 4, hc_l = tid & 15;
    const int n = n0 + n_l;
    const int hcol = hcg * 16 + hc_l;
    const float SCALE = 0.04419417382415922f;  // 1/sqrt(512)

    // preload Wh slice: Whs4[k*16+hc] = Whr4[k*512 + hcg*16+hc]
    for (int i = tid; i < 8192; i += 256) {
        int k = i >> 4, hc = i & 15;
        Whs4[i] = ((const float4*)g_Whr)[k * 512 + hcg * 16 + hc];
    }
    float c_reg = g_h[0][(long)n * HH + hcol];

    // initial partial scores from h0 (own 16-h slice)
    hn_s[n_l * 16 + hc_l] = c_reg;
    __syncthreads();
    {
        const float* ap = g_Ap + ((long)n * PP + hc_l) * HH + hcg * 16;
        float s = 0.f;
#pragma unroll
        for (int j = 0; j < 16; j++) s += __ldg(&ap[j]) * hn_s[n_l * 16 + j];
        __stcg(&g_scp[0][hcg][n][hc_l], s);
    }

    for (int t = 0; t < Tt; t++) {
        gridbar(tid, (unsigned)(t + 1) * 128u);

        // load full h_t (written by all hcg CTAs of this ng)
        const float4* hg = (const float4*)(g_h[t & 1] + (long)n0 * HH);
        float4* hs4 = (float4*)h_s;
#pragma unroll
        for (int q = 0; q < 8; q++)
            hs4[tid + q * 256] = __ldcg(&hg[tid + q * 256]);

        // gather partial scores (deterministic sum over 32 hcg slices)
        {
            const float* sp = &g_scp[t & 1][0][n][hc_l];
            float s = 0.f;
#pragma unroll
            for (int j = 0; j < 32; j++) s += __ldcg(sp + j * (Nn * PP));
            sc_s[n_l * 16 + hc_l] = s * SCALE;
        }
        __syncthreads();

        // softmax over 16 positions (each thread redundantly for its n)
        {
            float mx = -3.0e38f;
#pragma unroll
            for (int j = 0; j < 16; j++) mx = fmaxf(mx, sc_s[n_l * 16 + j]);
            float sum = 0.f;
#pragma unroll
            for (int j = 0; j < 16; j++) sum += __expf(sc_s[n_l * 16 + j] - mx);
            w_s[n_l * 16 + hc_l] = __expf(sc_s[n_l * 16 + hc_l] - mx) / sum;
        }
        __syncthreads();

        // gates
        float hnv;
        {
            long xb = ((long)(t * Nn + n)) * H4 + hcol;
            float a0 = __ldg(&g_xpr[xb]);
            float a1 = __ldg(&g_xpr[xb + 512]);
            float a2 = __ldg(&g_xpr[xb + 1024]);
            float a3 = __ldg(&g_xpr[xb + 1536]);
#pragma unroll
            for (int p = 0; p < PP; p++) {
                float wv = w_s[n_l * 16 + p];
                const float* awb = g_AW + ((long)(n * PP) + p) * H4 + hcol;
                a0 += wv * __ldg(awb);
                a1 += wv * __ldg(awb + 512);
                a2 += wv * __ldg(awb + 1024);
                a3 += wv * __ldg(awb + 1536);
            }
            const float4* hr4 = (const float4*)(h_s + n_l * HH);
            const float4* wr = Whs4 + hc_l;
#pragma unroll 4
            for (int k4 = 0; k4 < 128; k4++) {
                float4 hv = hr4[k4];
                float4 w0 = wr[(k4 * 4 + 0) * 16];
                float4 w1 = wr[(k4 * 4 + 1) * 16];
                float4 w2 = wr[(k4 * 4 + 2) * 16];
                float4 w3 = wr[(k4 * 4 + 3) * 16];
                a0 += hv.x*w0.x + hv.y*w1.x + hv.z*w2.x + hv.w*w3.x;
                a1 += hv.x*w0.y + hv.y*w1.y + hv.z*w2.y + hv.w*w3.y;
                a2 += hv.x*w0.z + hv.y*w1.z + hv.z*w2.z + hv.w*w3.z;
                a3 += hv.x*w0.w + hv.y*w1.w + hv.z*w2.w + hv.w*w3.w;
            }
            float ii = 1.f / (1.f + __expf(-a0));
            float ff = 1.f / (1.f + __expf(-a1));
            float oo = 1.f / (1.f + __expf(-a2));
            float gg = tanhf(a3);
            c_reg = ff * c_reg + ii * gg;
            hnv = oo * tanhf(c_reg);
            __stcg(&g_h[(t + 1) & 1][(long)n * HH + hcol], hnv);
            __stcg(&g_hn[((long)n * Tt + t) * HH + hcol], hnv);
        }

        // partial scores for t+1 from own h_next slice
        __syncthreads();
        hn_s[n_l * 16 + hc_l] = hnv;
        __syncthreads();
        if (t + 1 < Tt) {
            const float* ap = g_Ap + ((long)n * PP + hc_l) * HH + hcg * 16;
            float s = 0.f;
#pragma unroll
            for (int j = 0; j < 16; j++) s += __ldg(&ap[j]) * hn_s[n_l * 16 + j];
            __stcg(&g_scp[(t + 1) & 1][hcg][n][hc_l], s);
        }
    }
}

// ---- split hn into fp16 hi/lo planes ----
__global__ void k_split_hn()
{
    int i = blockIdx.x * 256 + threadIdx.x;
    float v = g_hn[i];
    __half h = __float2half_rn(v);
    g_hnH[i] = h;
    g_hnL[i] = __float2half_rn(v - __half2float(h));
}

// ---- transpose + split W_vocab: [k][n] f32 -> [n][k] half hi/lo ----
__global__ void __launch_bounds__(256) k_trans_wv(const float* __restrict__ Wv)
{
    __shared__ float t[32][33];
    int n0 = blockIdx.x * 32, k0 = blockIdx.y * 32;
    int tx = threadIdx.x & 31, ty = threadIdx.x >> 5;
#pragma unroll
    for (int j = 0; j < 4; j++)
        t[ty + 8*j][tx] = Wv[(size_t)(k0 + ty + 8*j) * VV + n0 + tx];
    __syncthreads();
#pragma unroll
    for (int j = 0; j < 4; j++) {
        int n = n0 + ty + 8*j, k = k0 + tx;
        float v = t[tx][ty + 8*j];
        __half h = __float2half_rn(v);
        g_WvH[(size_t)n * HH + k] = h;
        g_WvL[(size_t)n * HH + k] = __float2half_rn(v - __half2float(h));
    }
}

// ================= fp16-split HMMA vocab GEMM =================
#define VS_SMEM (3 * 32768)

__device__ __forceinline__ uint32_t s2u(const void* p) {
    uint32_t a;
    asm("{ .reg .u64 t; cvta.to.shared.u64 t, %1; cvt.u32.u64 %0, t; }" : "=r"(a) : "l"(p));
    return a;
}

#define CPA(dst, src) asm volatile("cp.async.cg.shared.global [%0], [%1], 16;" \
    :: "r"(dst), "l"(src) : "memory")
#define LDSM4(r, addr) asm volatile( \
    "ldmatrix.sync.aligned.m8n8.x4.shared.b16 {%0,%1,%2,%3}, [%4];" \
    : "=r"((r)[0]),"=r"((r)[1]),"=r"((r)[2]),"=r"((r)[3]) : "r"(addr))
#define MMA16816(c, a, b0, b1) asm volatile( \
    "mma.sync.aligned.m16n8k16.row.col.f32.f16.f16.f32 " \
    "{%0,%1,%2,%3}, {%4,%5,%6,%7}, {%8,%9}, {%0,%1,%2,%3};" \
    : "+f"((c)[0]), "+f"((c)[1]), "+f"((c)[2]), "+f"((c)[3]) \
    : "r"((a)[0]),"r"((a)[1]),"r"((a)[2]),"r"((a)[3]), "r"(b0),"r"(b1))

__global__ void __launch_bounds__(256, 2) k_vocab_mma(const float* __restrict__ bv,
                                                      float* __restrict__ out)
{
    extern __shared__ char sm[];
    const uint32_t sbase = s2u(sm);
    const int tid = threadIdx.x;
    const int lane = tid & 31, w = tid >> 5;
    const int m0 = blockIdx.x * 128, n0 = blockIdx.y * 128;
    const int wm = (w & 1) * 64, wn = (w >> 1) * 32;

    float acc[4][4][4];
#pragma unroll
    for (int i = 0; i < 4; i++)
#pragma unroll
        for (int j = 0; j < 4; j++)
#pragma unroll
            for (int q = 0; q < 4; q++) acc[i][j][q] = 0.f;

    const int r = tid >> 1, kk = tid & 1;
    const uint32_t swo = (uint32_t)(r * 32 + ((kk ^ ((r >> 2) & 1)) << 4));
    const __half* gAH = g_hnH + (size_t)(m0 + r) * HH + kk * 8;
    const __half* gAL = g_hnL + (size_t)(m0 + r) * HH + kk * 8;
    const __half* gBH = g_WvH + (size_t)(n0 + r) * HH + kk * 8;
    const __half* gBL = g_WvL + (size_t)(n0 + r) * HH + kk * 8;

    uint32_t aoff[4], boff[2];
#pragma unroll
    for (int mt = 0; mt < 4; mt++) {
        int ml = wm + mt * 16 + (lane & 15);
        int kl = lane >> 4;
        aoff[mt] = (uint32_t)(ml * 32 + ((kl ^ ((ml >> 2) & 1)) << 4));
    }
#pragma unroll
    for (int q = 0; q < 2; q++) {
        int g = lane >> 3;
        int nl = wn + q * 16 + ((g >> 1) * 8) + (lane & 7);
        int kl = g & 1;
        boff[q] = (uint32_t)(nl * 32 + ((kl ^ ((nl >> 2) & 1)) << 4));
    }

#define VS_ISSUE(ks) do {                                                     \
    uint32_t st = sbase + (uint32_t)((ks) % 3) * 32768u;                      \
    int kof = (ks) * 32;                                                      \
    CPA(st +     0 + swo, gAH + kof);  CPA(st +  4096 + swo, gAH + kof + 16); \
    CPA(st +  8192 + swo, gAL + kof);  CPA(st + 12288 + swo, gAL + kof + 16); \
    CPA(st + 16384 + swo, gBH + kof);  CPA(st + 20480 + swo, gBH + kof + 16); \
    CPA(st + 24576 + swo, gBL + kof);  CPA(st + 28672 + swo, gBL + kof + 16); \
    asm volatile("cp.async.commit_group;" ::: "memory");                      \
} while (0)

    VS_ISSUE(0); VS_ISSUE(1); VS_ISSUE(2);

    for (int ks = 0; ks < 16; ks++) {
        asm volatile("cp.async.wait_group 2;" ::: "memory");
        __syncthreads();
        uint32_t stb = sbase + (uint32_t)(ks % 3) * 32768u;
#pragma unroll
        for (int s = 0; s < 2; s++) {
            uint32_t sub = stb + (uint32_t)s * 4096u;
            uint32_t aH[4][4], aL[4][4], bH[2][4], bL[2][4];
#pragma unroll
            for (int mt = 0; mt < 4; mt++) {
                LDSM4(aH[mt], sub + aoff[mt]);
                LDSM4(aL[mt], sub + 8192 + aoff[mt]);
            }
#pragma unroll
            for (int q = 0; q < 2; q++) {
                LDSM4(bH[q], sub + 16384 + boff[q]);
                LDSM4(bL[q], sub + 24576 + boff[q]);
            }
#pragma unroll
            for (int mt = 0; mt < 4; mt++)
#pragma unroll
                for (int nt = 0; nt < 4; nt++) {
                    uint32_t b0h = bH[nt >> 1][(nt & 1) * 2];
                    uint32_t b1h = bH[nt >> 1][(nt & 1) * 2 + 1];
                    uint32_t b0l = bL[nt >> 1][(nt & 1) * 2];
                    uint32_t b1l = bL[nt >> 1][(nt & 1) * 2 + 1];
                    MMA16816(acc[mt][nt], aH[mt], b0h, b1h);
                    MMA16816(acc[mt][nt], aH[mt], b0l, b1l);
                    MMA16816(acc[mt][nt], aL[mt], b0h, b1h);
                }
        }
        __syncthreads();
        if (ks + 3 < 16) VS_ISSUE(ks + 3);
    }

#pragma unroll
    for (int mt = 0; mt < 4; mt++)
#pragma unroll
        for (int nt = 0; nt < 4; nt++) {
            int mrow = m0 + wm + mt * 16 + (lane >> 2);
            int ncol = n0 + wn + nt * 8 + 2 * (lane & 3);
            float b0 = __ldg(bv + ncol), b1 = __ldg(bv + ncol + 1);
            float2 v0 = make_float2(acc[mt][nt][0] + b0, acc[mt][nt][1] + b1);
            float2 v1 = make_float2(acc[mt][nt][2] + b0, acc[mt][nt][3] + b1);
            *(float2*)(out + (size_t)mrow * VV + ncol)       = v0;
            *(float2*)(out + (size_t)(mrow + 8) * VV + ncol) = v1;
        }
}

extern "C" void kernel_launch(void* const* d_in, const int* in_sizes, int n_in,
                              void* d_out, int out_size)
{
    const float* A      = (const float*)d_in[0];
    const int*   caps   = (const int*)  d_in[1];
    const float* conv_w = (const float*)d_in[2];
    const float* conv_b = (const float*)d_in[3];
    const float* Wx     = (const float*)d_in[4];
    const float* Wh     = (const float*)d_in[5];
    const float* Wattn  = (const float*)d_in[6];
    const float* b      = (const float*)d_in[7];
    const float* Wemb   = (const float*)d_in[8];
    const float* Wv     = (const float*)d_in[9];
    const float* bv     = (const float*)d_in[10];
    float* out = (float*)d_out;

    cudaFuncSetAttribute(k_vocab_mma, cudaFuncAttributeMaxDynamicSharedMemorySize, VS_SMEM);
    cudaFuncSetAttribute(k3_lstm,     cudaFuncAttributeMaxDynamicSharedMemorySize, LS_SMEM);

    k_trans_wv<<<dim3(1000, 16), 256>>>(Wv);
    k1_conv<<<dim3(8, 16), 256>>>(A, conv_w, conv_b);
    k1b_h0<<<64, 128>>>();
    k_whr<<<1024, 256>>>(Wh);
    k_gemm_aw<<<dim3(16, 8), 256>>>(Wattn);
    k_gemm_x<<<dim3(16, 16), 256>>>(Wemb, Wx, b, caps);
    k_reset<<<1, 1>>>();
    k3_lstm<<<128, 256, LS_SMEM>>>();
    k_split_hn<<<4096, 256>>>();
    k_vocab_mma<<<dim3(16, 250), 256, VS_SMEM>>>(bv, out);
}

// round 6
// speedup vs baseline: 3.0553x; 1.1529x over previous
#include <cuda_runtime.h>
#include <cuda_bf16.h>
#include <cuda_fp16.h>
#include <math.h>
#include <cstdint>

#define Nn   64
#define Tt   32
#define DA   1280
#define PP   16
#define WDIM 300
#define HH   512
#define H4   2048
#define VV   32000

__device__ float    g_Ap [Nn*PP*HH];
__device__ float    g_AW [Nn*PP*H4];
__device__ float    g_Whr[HH*H4];
__device__ float    g_xpr[(Nn*Tt)*H4];
__device__ float    g_h  [2][Nn*HH];
__device__ float    g_scp[2][32][Nn][PP];
__device__ unsigned g_bar;
__device__ __half   g_hnH[(Nn*Tt)*HH];
__device__ __half   g_hnL[(Nn*Tt)*HH];
__device__ __half   g_WvH[(size_t)VV*HH];

// ---- K1: A_proj[r=n*16+p][h] = sum_c A[n][c][p]*conv_w[h][c] + conv_b[h] ----
__global__ void __launch_bounds__(256) k1_conv(const float* __restrict__ A,
                                               const float* __restrict__ Wc,
                                               const float* __restrict__ bc)
{
    __shared__ float As[16][68];
    __shared__ float Ws[16][68];
    int tid = threadIdx.x;
    int m0 = blockIdx.y * 64, h0 = blockIdx.x * 64;
    int tm = (tid >> 4) * 4, tn = (tid & 15) * 4;
    float acc[4][4] = {};
    int mL = tid & 63, kA = tid >> 6;
    int kW = tid & 15, hW = tid >> 4;
    int nA = (m0 + mL) >> 4, pA = (m0 + mL) & 15;
    const float* Abase = A + (long)nA * (DA * PP) + pA;
    for (int c0 = 0; c0 < DA; c0 += 16) {
#pragma unroll
        for (int it = 0; it < 4; it++) {
            int k = kA + it * 4;
            As[k][mL] = Abase[(c0 + k) * PP];
        }
#pragma unroll
        for (int it = 0; it < 4; it++) {
            int h = hW + it * 16;
            Ws[kW][h] = Wc[(long)(h0 + h) * DA + c0 + kW];
        }
        __syncthreads();
#pragma unroll
        for (int k = 0; k < 16; k++) {
            float4 a = *(const float4*)&As[k][tm];
            float4 b = *(const float4*)&Ws[k][tn];
            float av[4] = {a.x,a.y,a.z,a.w};
            float bv[4] = {b.x,b.y,b.z,b.w};
#pragma unroll
            for (int i = 0; i < 4; i++)
#pragma unroll
                for (int j = 0; j < 4; j++) acc[i][j] += av[i] * bv[j];
        }
        __syncthreads();
    }
#pragma unroll
    for (int i = 0; i < 4; i++) {
        int r = m0 + tm + i;
#pragma unroll
        for (int j = 0; j < 4; j++)
            g_Ap[(long)r * HH + h0 + tn + j] = acc[i][j] + bc[h0 + tn + j];
    }
}

// ---- h0 = mean over 16 spatial positions ----
__global__ void k1b_h0()
{
    int n = blockIdx.x, t = threadIdx.x;
    const float4* ap = (const float4*)(g_Ap + (long)n * PP * HH);
    float4 s = make_float4(0.f,0.f,0.f,0.f);
#pragma unroll
    for (int p = 0; p < PP; p++) {
        float4 v = ap[p * 128 + t];
        s.x += v.x; s.y += v.y; s.z += v.z; s.w += v.w;
    }
    s.x *= 0.0625f; s.y *= 0.0625f; s.z *= 0.0625f; s.w *= 0.0625f;
    ((float4*)(g_h[0] + (long)n * HH))[t] = s;
}

// ---- gate-interleave Wh ----
__global__ void k_whr(const float* __restrict__ Wh)
{
    int idx = blockIdx.x * 256 + threadIdx.x;
    int k = idx >> 9, h = idx & 511;
    const float* src = Wh + (long)k * H4 + h;
    ((float4*)g_Whr)[idx] = make_float4(src[0], src[512], src[1024], src[1536]);
}

// ---- generic 128x128 SGEMM body (AW and X pre-GEMMs) ----
template<bool GATHER, bool BIAS>
__device__ __forceinline__ void gemm128_body(
    const float* __restrict__ Amat, int lda, int Kd,
    const float* __restrict__ Bmat, int ldb,
    const float* __restrict__ bias,
    float* __restrict__ C, int ldc,
    const int* __restrict__ caps)
{
    __shared__ float As[16][132];
    __shared__ float Bs[16][128];
    int tid = threadIdx.x;
    int m0 = blockIdx.y * 128, c0 = blockIdx.x * 128;
    int tm = (tid >> 4) * 8, tn = (tid & 15) * 8;
    float acc[8][8] = {};
    int mA = tid >> 2, kq = (tid & 3) * 4;
    const float *arow0, *arow1;
    {
        int r0 = m0 + mA, r1 = r0 + 64;
        if (GATHER) {
            arow0 = Amat + (long)caps[(r0 & 63) * Tt + (r0 >> 6)] * lda;
            arow1 = Amat + (long)caps[(r1 & 63) * Tt + (r1 >> 6)] * lda;
        } else {
            arow0 = Amat + (long)r0 * lda;
            arow1 = Amat + (long)r1 * lda;
        }
    }
    int kB = tid >> 5, cB = (tid & 31) * 4;
    int nchunk = (Kd + 15) >> 4;
    for (int ch = 0; ch < nchunk; ch++) {
        int k0 = ch * 16;
        if (k0 + 16 <= Kd) {
            float4 a0 = *(const float4*)(arow0 + k0 + kq);
            float4 a1 = *(const float4*)(arow1 + k0 + kq);
            As[kq+0][mA] = a0.x; As[kq+1][mA] = a0.y;
            As[kq+2][mA] = a0.z; As[kq+3][mA] = a0.w;
            As[kq+0][mA+64] = a1.x; As[kq+1][mA+64] = a1.y;
            As[kq+2][mA+64] = a1.z; As[kq+3][mA+64] = a1.w;
        } else {
#pragma unroll
            for (int i = 0; i < 4; i++) {
                int k = k0 + kq + i;
                As[kq+i][mA]    = (k < Kd) ? arow0[k] : 0.f;
                As[kq+i][mA+64] = (k < Kd) ? arow1[k] : 0.f;
            }
        }
#pragma unroll
        for (int it = 0; it < 2; it++) {
            int k = k0 + kB + it * 8;
            float4 bv = (k < Kd) ? *(const float4*)(Bmat + (long)k * ldb + c0 + cB)
                                 : make_float4(0.f,0.f,0.f,0.f);
            *(float4*)&Bs[kB + it*8][cB] = bv;
        }
        __syncthreads();
#pragma unroll
        for (int k = 0; k < 16; k++) {
            float4 a0 = *(const float4*)&As[k][tm];
            float4 a1 = *(const float4*)&As[k][tm+4];
            float4 b0 = *(const float4*)&Bs[k][tn];
            float4 b1 = *(const float4*)&Bs[k][tn+4];
            float av[8] = {a0.x,a0.y,a0.z,a0.w,a1.x,a1.y,a1.z,a1.w};
            float bv[8] = {b0.x,b0.y,b0.z,b0.w,b1.x,b1.y,b1.z,b1.w};
#pragma unroll
            for (int i = 0; i < 8; i++)
#pragma unroll
                for (int j = 0; j < 8; j++) acc[i][j] += av[i] * bv[j];
        }
        __syncthreads();
    }
    float4 bia0 = make_float4(0,0,0,0), bia1 = bia0;
    if (BIAS) {
        bia0 = *(const float4*)(bias + c0 + tn);
        bia1 = *(const float4*)(bias + c0 + tn + 4);
    }
#pragma unroll
    for (int i = 0; i < 8; i++) {
        long r = m0 + tm + i;
        float4 o0 = make_float4(acc[i][0]+bia0.x, acc[i][1]+bia0.y,
                                acc[i][2]+bia0.z, acc[i][3]+bia0.w);
        float4 o1 = make_float4(acc[i][4]+bia1.x, acc[i][5]+bia1.y,
                                acc[i][6]+bia1.z, acc[i][7]+bia1.w);
        *(float4*)(C + r * ldc + c0 + tn)     = o0;
        *(float4*)(C + r * ldc + c0 + tn + 4) = o1;
    }
}

__global__ void __launch_bounds__(256, 2) k_gemm_aw(const float* __restrict__ Wattn)
{ gemm128_body<false,false>(g_Ap, HH, HH, Wattn, H4, nullptr, g_AW, H4, nullptr); }

__global__ void __launch_bounds__(256, 2) k_gemm_x(const float* __restrict__ Wemb,
                                                   const float* __restrict__ Wx,
                                                   const float* __restrict__ bb,
                                                   const int*   __restrict__ caps)
{ gemm128_body<true,true>(Wemb, WDIM, WDIM, Wx, H4, bb, g_xpr, H4, caps); }

__global__ void k_reset() { g_bar = 0u; }

// ================= persistent attention-LSTM (SMEM-resident Wh) =================
#define LS_SMEM 166912

__global__ void __launch_bounds__(256) k3_lstm()
{
    extern __shared__ char sm[];
    float4* Whs4 = (float4*)sm;                    // [512][16] float4 = 128KB
    float*  h_s  = (float*)(sm + 131072);          // [16][512]        = 32KB
    float*  sc_s = (float*)(sm + 163840);
    float*  w_s  = (float*)(sm + 164864);
    float*  hn_s = (float*)(sm + 165888);

    const int tid = threadIdx.x, blk = blockIdx.x;
    const int ng = blk >> 5, hcg = blk & 31;
    const int n0 = ng * 16;
    const int n_l = tid >> 4, hc_l = tid & 15;
    const int n = n0 + n_l;
    const int hcol = hcg * 16 + hc_l;
    const float SCALE = 0.04419417382415922f;  // 1/sqrt(512)

    for (int i = tid; i < 8192; i += 256) {
        int k = i >> 4, hc = i & 15;
        Whs4[i] = ((const float4*)g_Whr)[k * 512 + hcg * 16 + hc];
    }
    float c_reg = g_h[0][(long)n * HH + hcol];

    hn_s[n_l * 16 + hc_l] = c_reg;
    __syncthreads();
    {
        const float* ap = g_Ap + ((long)n * PP + hc_l) * HH + hcg * 16;
        float s = 0.f;
#pragma unroll
        for (int j = 0; j < 16; j++) s += __ldg(&ap[j]) * hn_s[n_l * 16 + j];
        __stcg(&g_scp[0][hcg][n][hc_l], s);
    }

    for (int t = 0; t < Tt; t++) {
        // grid barrier
        __threadfence();
        __syncthreads();
        if (tid == 0) {
            atomicAdd(&g_bar, 1u);
            unsigned target = (unsigned)(t + 1) * 128u;
            while (*(volatile unsigned*)&g_bar < target) { }
        }
        __syncthreads();

        const float4* hg = (const float4*)(g_h[t & 1] + (long)n0 * HH);
        float4* hs4 = (float4*)h_s;
#pragma unroll
        for (int q = 0; q < 8; q++)
            hs4[tid + q * 256] = __ldcg(&hg[tid + q * 256]);

        {
            const float* sp = &g_scp[t & 1][0][n][hc_l];
            float s = 0.f;
#pragma unroll
            for (int j = 0; j < 32; j++) s += __ldcg(sp + j * (Nn * PP));
            sc_s[n_l * 16 + hc_l] = s * SCALE;
        }
        __syncthreads();

        {
            float mx = -3.0e38f;
#pragma unroll
            for (int j = 0; j < 16; j++) mx = fmaxf(mx, sc_s[n_l * 16 + j]);
            float sum = 0.f;
#pragma unroll
            for (int j = 0; j < 16; j++) sum += __expf(sc_s[n_l * 16 + j] - mx);
            w_s[n_l * 16 + hc_l] = __expf(sc_s[n_l * 16 + hc_l] - mx) / sum;
        }
        __syncthreads();

        float hnv;
        {
            long xb = ((long)(t * Nn + n)) * H4 + hcol;
            float a0 = __ldg(&g_xpr[xb]);
            float a1 = __ldg(&g_xpr[xb + 512]);
            float a2 = __ldg(&g_xpr[xb + 1024]);
            float a3 = __ldg(&g_xpr[xb + 1536]);
#pragma unroll
            for (int p = 0; p < PP; p++) {
                float wv = w_s[n_l * 16 + p];
                const float* awb = g_AW + ((long)(n * PP) + p) * H4 + hcol;
                a0 += wv * __ldg(awb);
                a1 += wv * __ldg(awb + 512);
                a2 += wv * __ldg(awb + 1024);
                a3 += wv * __ldg(awb + 1536);
            }
            const float4* hr4 = (const float4*)(h_s + n_l * HH);
            const float4* wr = Whs4 + hc_l;
#pragma unroll 4
            for (int k4 = 0; k4 < 128; k4++) {
                float4 hv = hr4[k4];
                float4 w0 = wr[(k4 * 4 + 0) * 16];
                float4 w1 = wr[(k4 * 4 + 1) * 16];
                float4 w2 = wr[(k4 * 4 + 2) * 16];
                float4 w3 = wr[(k4 * 4 + 3) * 16];
                a0 += hv.x*w0.x + hv.y*w1.x + hv.z*w2.x + hv.w*w3.x;
                a1 += hv.x*w0.y + hv.y*w1.y + hv.z*w2.y + hv.w*w3.y;
                a2 += hv.x*w0.z + hv.y*w1.z + hv.z*w2.z + hv.w*w3.z;
                a3 += hv.x*w0.w + hv.y*w1.w + hv.z*w2.w + hv.w*w3.w;
            }
            float ii = 1.f / (1.f + __expf(-a0));
            float ff = 1.f / (1.f + __expf(-a1));
            float oo = 1.f / (1.f + __expf(-a2));
            float gg = tanhf(a3);
            c_reg = ff * c_reg + ii * gg;
            hnv = oo * tanhf(c_reg);
            __stcg(&g_h[(t + 1) & 1][(long)n * HH + hcol], hnv);
            // fused fp16 hi/lo split of hn (consumed by vocab GEMM)
            long hi = ((long)n * Tt + t) * HH + hcol;
            __half hh = __float2half_rn(hnv);
            __stcg(&g_hnH[hi], hh);
            __stcg(&g_hnL[hi], __float2half_rn(hnv - __half2float(hh)));
        }

        __syncthreads();
        hn_s[n_l * 16 + hc_l] = hnv;
        __syncthreads();
        if (t + 1 < Tt) {
            const float* ap = g_Ap + ((long)n * PP + hc_l) * HH + hcg * 16;
            float s = 0.f;
#pragma unroll
            for (int j = 0; j < 16; j++) s += __ldg(&ap[j]) * hn_s[n_l * 16 + j];
            __stcg(&g_scp[(t + 1) & 1][hcg][n][hc_l], s);
        }
    }
}

// ---- transpose W_vocab: [k][n] f32 -> [n][k] half (hi plane only) ----
__global__ void __launch_bounds__(256) k_trans_wv(const float* __restrict__ Wv)
{
    __shared__ float t[32][33];
    int n0 = blockIdx.x * 32, k0 = blockIdx.y * 32;
    int tx = threadIdx.x & 31, ty = threadIdx.x >> 5;
#pragma unroll
    for (int j = 0; j < 4; j++)
        t[ty + 8*j][tx] = Wv[(size_t)(k0 + ty + 8*j) * VV + n0 + tx];
    __syncthreads();
#pragma unroll
    for (int j = 0; j < 4; j++) {
        int n = n0 + ty + 8*j, k = k0 + tx;
        g_WvH[(size_t)n * HH + k] = __float2half_rn(t[tx][ty + 8*j]);
    }
}

// ================= fp16-split HMMA vocab GEMM (2-pass: (aH+aL)*bH) =================
// stage = A-hi 8KB | A-lo 8KB | B-hi 8KB = 24KB; 4-stage pipeline = 96KB
#define VS_STG  24576
#define VS_SMEM (4 * VS_STG)

__device__ __forceinline__ uint32_t s2u(const void* p) {
    uint32_t a;
    asm("{ .reg .u64 t; cvta.to.shared.u64 t, %1; cvt.u32.u64 %0, t; }" : "=r"(a) : "l"(p));
    return a;
}

#define CPA(dst, src) asm volatile("cp.async.cg.shared.global [%0], [%1], 16;" \
    :: "r"(dst), "l"(src) : "memory")
#define LDSM4(r, addr) asm volatile( \
    "ldmatrix.sync.aligned.m8n8.x4.shared.b16 {%0,%1,%2,%3}, [%4];" \
    : "=r"((r)[0]),"=r"((r)[1]),"=r"((r)[2]),"=r"((r)[3]) : "r"(addr))
#define MMA16816(c, a, b0, b1) asm volatile( \
    "mma.sync.aligned.m16n8k16.row.col.f32.f16.f16.f32 " \
    "{%0,%1,%2,%3}, {%4,%5,%6,%7}, {%8,%9}, {%0,%1,%2,%3};" \
    : "+f"((c)[0]), "+f"((c)[1]), "+f"((c)[2]), "+f"((c)[3]) \
    : "r"((a)[0]),"r"((a)[1]),"r"((a)[2]),"r"((a)[3]), "r"(b0),"r"(b1))

__global__ void __launch_bounds__(256, 2) k_vocab_mma(const float* __restrict__ bv,
                                                      float* __restrict__ out)
{
    extern __shared__ char sm[];
    const uint32_t sbase = s2u(sm);
    const int tid = threadIdx.x;
    const int lane = tid & 31, w = tid >> 5;
    const int m0 = blockIdx.x * 128, n0 = blockIdx.y * 128;
    const int wm = (w & 1) * 64, wn = (w >> 1) * 32;

    float acc[4][4][4];
#pragma unroll
    for (int i = 0; i < 4; i++)
#pragma unroll
        for (int j = 0; j < 4; j++)
#pragma unroll
            for (int q = 0; q < 4; q++) acc[i][j][q] = 0.f;

    const int r = tid >> 1, kk = tid & 1;
    const uint32_t swo = (uint32_t)(r * 32 + ((kk ^ ((r >> 2) & 1)) << 4));
    const __half* gAH = g_hnH + (size_t)(m0 + r) * HH + kk * 8;
    const __half* gAL = g_hnL + (size_t)(m0 + r) * HH + kk * 8;
    const __half* gBH = g_WvH + (size_t)(n0 + r) * HH + kk * 8;

    uint32_t aoff[4], boff[2];
#pragma unroll
    for (int mt = 0; mt < 4; mt++) {
        int ml = wm + mt * 16 + (lane & 15);
        int kl = lane >> 4;
        aoff[mt] = (uint32_t)(ml * 32 + ((kl ^ ((ml >> 2) & 1)) << 4));
    }
#pragma unroll
    for (int q = 0; q < 2; q++) {
        int g = lane >> 3;
        int nl = wn + q * 16 + ((g >> 1) * 8) + (lane & 7);
        int kl = g & 1;
        boff[q] = (uint32_t)(nl * 32 + ((kl ^ ((nl >> 2) & 1)) << 4));
    }

#define VS_ISSUE(ks) do {                                                     \
    uint32_t st = sbase + (uint32_t)((ks) % 4) * VS_STG;                      \
    int kof = (ks) * 32;                                                      \
    CPA(st +     0 + swo, gAH + kof);  CPA(st +  4096 + swo, gAH + kof + 16); \
    CPA(st +  8192 + swo, gAL + kof);  CPA(st + 12288 + swo, gAL + kof + 16); \
    CPA(st + 16384 + swo, gBH + kof);  CPA(st + 20480 + swo, gBH + kof + 16); \
    asm volatile("cp.async.commit_group;" ::: "memory");                      \
} while (0)

    VS_ISSUE(0); VS_ISSUE(1); VS_ISSUE(2);

    for (int ks = 0; ks < 16; ks++) {
        asm volatile("cp.async.wait_group 2;" ::: "memory");
        __syncthreads();
        uint32_t stb = sbase + (uint32_t)(ks % 4) * VS_STG;
#pragma unroll
        for (int s = 0; s < 2; s++) {
            uint32_t sub = stb + (uint32_t)s * 4096u;
            uint32_t aH[4][4], aL[4][4], bH[2][4];
#pragma unroll
            for (int mt = 0; mt < 4; mt++) {
                LDSM4(aH[mt], sub + aoff[mt]);
                LDSM4(aL[mt], sub + 8192 + aoff[mt]);
            }
#pragma unroll
            for (int q = 0; q < 2; q++)
                LDSM4(bH[q], sub + 16384 + boff[q]);
#pragma unroll
            for (int mt = 0; mt < 4; mt++)
#pragma unroll
                for (int nt = 0; nt < 4; nt++) {
                    uint32_t b0h = bH[nt >> 1][(nt & 1) * 2];
                    uint32_t b1h = bH[nt >> 1][(nt & 1) * 2 + 1];
                    MMA16816(acc[mt][nt], aH[mt], b0h, b1h);
                    MMA16816(acc[mt][nt], aL[mt], b0h, b1h);
                }
        }
        __syncthreads();
        if (ks + 3 < 16) VS_ISSUE(ks + 3);
    }

#pragma unroll
    for (int mt = 0; mt < 4; mt++)
#pragma unroll
        for (int nt = 0; nt < 4; nt++) {
            int mrow = m0 + wm + mt * 16 + (lane >> 2);
            int ncol = n0 + wn + nt * 8 + 2 * (lane & 3);
            float b0 = __ldg(bv + ncol), b1 = __ldg(bv + ncol + 1);
            float2 v0 = make_float2(acc[mt][nt][0] + b0, acc[mt][nt][1] + b1);
            float2 v1 = make_float2(acc[mt][nt][2] + b0, acc[mt][nt][3] + b1);
            *(float2*)(out + (size_t)mrow * VV + ncol)       = v0;
            *(float2*)(out + (size_t)(mrow + 8) * VV + ncol) = v1;
        }
}

extern "C" void kernel_launch(void* const* d_in, const int* in_sizes, int n_in,
                              void* d_out, int out_size)
{
    const float* A      = (const float*)d_in[0];
    const int*   caps   = (const int*)  d_in[1];
    const float* conv_w = (const float*)d_in[2];
    const float* conv_b = (const float*)d_in[3];
    const float* Wx     = (const float*)d_in[4];
    const float* Wh     = (const float*)d_in[5];
    const float* Wattn  = (const float*)d_in[6];
    const float* b      = (const float*)d_in[7];
    const float* Wemb   = (const float*)d_in[8];
    const float* Wv     = (const float*)d_in[9];
    const float* bv     = (const float*)d_in[10];
    float* out = (float*)d_out;

    cudaFuncSetAttribute(k_vocab_mma, cudaFuncAttributeMaxDynamicSharedMemorySize, VS_SMEM);
    cudaFuncSetAttribute(k3_lstm,     cudaFuncAttributeMaxDynamicSharedMemorySize, LS_SMEM);

    k_trans_wv<<<dim3(1000, 16), 256>>>(Wv);
    k1_conv<<<dim3(8, 16), 256>>>(A, conv_w, conv_b);
    k1b_h0<<<64, 128>>>();
    k_whr<<<1024, 256>>>(Wh);
    k_gemm_aw<<<dim3(16, 8), 256>>>(Wattn);
    k_gemm_x<<<dim3(16, 16), 256>>>(Wemb, Wx, b, caps);
    k_reset<<<1, 1>>>();
    k3_lstm<<<128, 256, LS_SMEM>>>();
    k_vocab_mma<<<dim3(16, 250), 256, VS_SMEM>>>(bv, out);
}

// round 9
// speedup vs baseline: 3.3681x; 1.1024x over previous
#include <cuda_runtime.h>
#include <cuda_bf16.h>
#include <cuda_fp16.h>
#include <math.h>
#include <cstdint>

#define Nn   64
#define Tt   32
#define DA   1280
#define PP   16
#define WDIM 300
#define HH   512
#define H4   2048
#define VV   32000

__device__ float    g_Ap [Nn*PP*HH];
__device__ float    g_AW [Nn*PP*H4];
__device__ float    g_Whr[HH*H4];
__device__ float    g_xpr[(Nn*Tt)*H4];
__device__ float    g_h  [2][Nn*HH];
__device__ float    g_scp[2][32][Nn][PP];
__device__ unsigned g_bar;
__device__ __half   g_hnH[(Nn*Tt)*HH];
__device__ __half   g_WvH[(size_t)VV*HH];

// ---- K1: A_proj[r=n*16+p][h] = sum_c A[n][c][p]*conv_w[h][c] + conv_b[h] ----
__global__ void __launch_bounds__(256) k1_conv(const float* __restrict__ A,
                                               const float* __restrict__ Wc,
                                               const float* __restrict__ bc)
{
    __shared__ float As[16][68];
    __shared__ float Ws[16][68];
    int tid = threadIdx.x;
    int m0 = blockIdx.y * 64, h0 = blockIdx.x * 64;
    int tm = (tid >> 4) * 4, tn = (tid & 15) * 4;
    float acc[4][4] = {};
    int mL = tid & 63, kA = tid >> 6;
    int kW = tid & 15, hW = tid >> 4;
    int nA = (m0 + mL) >> 4, pA = (m0 + mL) & 15;
    const float* Abase = A + (long)nA * (DA * PP) + pA;
    for (int c0 = 0; c0 < DA; c0 += 16) {
#pragma unroll
        for (int it = 0; it < 4; it++) {
            int k = kA + it * 4;
            As[k][mL] = Abase[(c0 + k) * PP];
        }
#pragma unroll
        for (int it = 0; it < 4; it++) {
            int h = hW + it * 16;
            Ws[kW][h] = Wc[(long)(h0 + h) * DA + c0 + kW];
        }
        __syncthreads();
#pragma unroll
        for (int k = 0; k < 16; k++) {
            float4 a = *(const float4*)&As[k][tm];
            float4 b = *(const float4*)&Ws[k][tn];
            float av[4] = {a.x,a.y,a.z,a.w};
            float bv[4] = {b.x,b.y,b.z,b.w};
#pragma unroll
            for (int i = 0; i < 4; i++)
#pragma unroll
                for (int j = 0; j < 4; j++) acc[i][j] += av[i] * bv[j];
        }
        __syncthreads();
    }
#pragma unroll
    for (int i = 0; i < 4; i++) {
        int r = m0 + tm + i;
#pragma unroll
        for (int j = 0; j < 4; j++)
            g_Ap[(long)r * HH + h0 + tn + j] = acc[i][j] + bc[h0 + tn + j];
    }
}

// ---- h0 = mean over 16 spatial positions ----
__global__ void k1b_h0()
{
    int n = blockIdx.x, t = threadIdx.x;
    const float4* ap = (const float4*)(g_Ap + (long)n * PP * HH);
    float4 s = make_float4(0.f,0.f,0.f,0.f);
#pragma unroll
    for (int p = 0; p < PP; p++) {
        float4 v = ap[p * 128 + t];
        s.x += v.x; s.y += v.y; s.z += v.z; s.w += v.w;
    }
    s.x *= 0.0625f; s.y *= 0.0625f; s.z *= 0.0625f; s.w *= 0.0625f;
    ((float4*)(g_h[0] + (long)n * HH))[t] = s;
}

// ---- gate-interleave Wh ----
__global__ void k_whr(const float* __restrict__ Wh)
{
    int idx = blockIdx.x * 256 + threadIdx.x;
    int k = idx >> 9, h = idx & 511;
    const float* src = Wh + (long)k * H4 + h;
    ((float4*)g_Whr)[idx] = make_float4(src[0], src[512], src[1024], src[1536]);
}

// ---- generic 128x128 SGEMM body (AW and X pre-GEMMs) ----
template<bool GATHER, bool BIAS>
__device__ __forceinline__ void gemm128_body(
    const float* __restrict__ Amat, int lda, int Kd,
    const float* __restrict__ Bmat, int ldb,
    const float* __restrict__ bias,
    float* __restrict__ C, int ldc,
    const int* __restrict__ caps)
{
    __shared__ float As[16][132];
    __shared__ float Bs[16][128];
    int tid = threadIdx.x;
    int m0 = blockIdx.y * 128, c0 = blockIdx.x * 128;
    int tm = (tid >> 4) * 8, tn = (tid & 15) * 8;
    float acc[8][8] = {};
    int mA = tid >> 2, kq = (tid & 3) * 4;
    const float *arow0, *arow1;
    {
        int r0 = m0 + mA, r1 = r0 + 64;
        if (GATHER) {
            arow0 = Amat + (long)caps[(r0 & 63) * Tt + (r0 >> 6)] * lda;
            arow1 = Amat + (long)caps[(r1 & 63) * Tt + (r1 >> 6)] * lda;
        } else {
            arow0 = Amat + (long)r0 * lda;
            arow1 = Amat + (long)r1 * lda;
        }
    }
    int kB = tid >> 5, cB = (tid & 31) * 4;
    int nchunk = (Kd + 15) >> 4;
    for (int ch = 0; ch < nchunk; ch++) {
        int k0 = ch * 16;
        if (k0 + 16 <= Kd) {
            float4 a0 = *(const float4*)(arow0 + k0 + kq);
            float4 a1 = *(const float4*)(arow1 + k0 + kq);
            As[kq+0][mA] = a0.x; As[kq+1][mA] = a0.y;
            As[kq+2][mA] = a0.z; As[kq+3][mA] = a0.w;
            As[kq+0][mA+64] = a1.x; As[kq+1][mA+64] = a1.y;
            As[kq+2][mA+64] = a1.z; As[kq+3][mA+64] = a1.w;
        } else {
#pragma unroll
            for (int i = 0; i < 4; i++) {
                int k = k0 + kq + i;
                As[kq+i][mA]    = (k < Kd) ? arow0[k] : 0.f;
                As[kq+i][mA+64] = (k < Kd) ? arow1[k] : 0.f;
            }
        }
#pragma unroll
        for (int it = 0; it < 2; it++) {
            int k = k0 + kB + it * 8;
            float4 bv = (k < Kd) ? *(const float4*)(Bmat + (long)k * ldb + c0 + cB)
                                 : make_float4(0.f,0.f,0.f,0.f);
            *(float4*)&Bs[kB + it*8][cB] = bv;
        }
        __syncthreads();
#pragma unroll
        for (int k = 0; k < 16; k++) {
            float4 a0 = *(const float4*)&As[k][tm];
            float4 a1 = *(const float4*)&As[k][tm+4];
            float4 b0 = *(const float4*)&Bs[k][tn];
            float4 b1 = *(const float4*)&Bs[k][tn+4];
            float av[8] = {a0.x,a0.y,a0.z,a0.w,a1.x,a1.y,a1.z,a1.w};
            float bv[8] = {b0.x,b0.y,b0.z,b0.w,b1.x,b1.y,b1.z,b1.w};
#pragma unroll
            for (int i = 0; i < 8; i++)
#pragma unroll
                for (int j = 0; j < 8; j++) acc[i][j] += av[i] * bv[j];
        }
        __syncthreads();
    }
    float4 bia0 = make_float4(0,0,0,0), bia1 = bia0;
    if (BIAS) {
        bia0 = *(const float4*)(bias + c0 + tn);
        bia1 = *(const float4*)(bias + c0 + tn + 4);
    }
#pragma unroll
    for (int i = 0; i < 8; i++) {
        long r = m0 + tm + i;
        float4 o0 = make_float4(acc[i][0]+bia0.x, acc[i][1]+bia0.y,
                                acc[i][2]+bia0.z, acc[i][3]+bia0.w);
        float4 o1 = make_float4(acc[i][4]+bia1.x, acc[i][5]+bia1.y,
                                acc[i][6]+bia1.z, acc[i][7]+bia1.w);
        *(float4*)(C + r * ldc + c0 + tn)     = o0;
        *(float4*)(C + r * ldc + c0 + tn + 4) = o1;
    }
}

__global__ void __launch_bounds__(256, 2) k_gemm_aw(const float* __restrict__ Wattn)
{ gemm128_body<false,false>(g_Ap, HH, HH, Wattn, H4, nullptr, g_AW, H4, nullptr); }

__global__ void __launch_bounds__(256, 2) k_gemm_x(const float* __restrict__ Wemb,
                                                   const float* __restrict__ Wx,
                                                   const float* __restrict__ bb,
                                                   const int*   __restrict__ caps)
{ gemm128_body<true,true>(Wemb, WDIM, WDIM, Wx, H4, bb, g_xpr, H4, caps); }

__global__ void k_reset() { g_bar = 0u; }

// ================= persistent attention-LSTM (SMEM-resident Wh) =================
#define LS_SMEM 166912

__global__ void __launch_bounds__(256) k3_lstm()
{
    extern __shared__ char sm[];
    float4* Whs4 = (float4*)sm;                    // [512][16] float4 = 128KB
    float*  h_s  = (float*)(sm + 131072);          // [16][512]        = 32KB
    float*  sc_s = (float*)(sm + 163840);
    float*  w_s  = (float*)(sm + 164864);
    float*  hn_s = (float*)(sm + 165888);

    const int tid = threadIdx.x, blk = blockIdx.x;
    const int ng = blk >> 5, hcg = blk & 31;
    const int n0 = ng * 16;
    const int n_l = tid >> 4, hc_l = tid & 15;
    const int n = n0 + n_l;
    const int hcol = hcg * 16 + hc_l;
    const float SCALE = 0.04419417382415922f;  // 1/sqrt(512)

    for (int i = tid; i < 8192; i += 256) {
        int k = i >> 4, hc = i & 15;
        Whs4[i] = ((const float4*)g_Whr)[k * 512 + hcg * 16 + hc];
    }
    float c_reg = g_h[0][(long)n * HH + hcol];

    hn_s[n_l * 16 + hc_l] = c_reg;
    __syncthreads();
    {
        const float* ap = g_Ap + ((long)n * PP + hc_l) * HH + hcg * 16;
        float s = 0.f;
#pragma unroll
        for (int j = 0; j < 16; j++) s += __ldg(&ap[j]) * hn_s[n_l * 16 + j];
        __stcg(&g_scp[0][hcg][n][hc_l], s);
    }

    for (int t = 0; t < Tt; t++) {
        // grid barrier
        __threadfence();
        __syncthreads();
        if (tid == 0) {
            atomicAdd(&g_bar, 1u);
            unsigned target = (unsigned)(t + 1) * 128u;
            while (*(volatile unsigned*)&g_bar < target) { }
        }
        __syncthreads();

        const float4* hg = (const float4*)(g_h[t & 1] + (long)n0 * HH);
        float4* hs4 = (float4*)h_s;
#pragma unroll
        for (int q = 0; q < 8; q++)
            hs4[tid + q * 256] = __ldcg(&hg[tid + q * 256]);

        {
            const float* sp = &g_scp[t & 1][0][n][hc_l];
            float s = 0.f;
#pragma unroll
            for (int j = 0; j < 32; j++) s += __ldcg(sp + j * (Nn * PP));
            sc_s[n_l * 16 + hc_l] = s * SCALE;
        }
        __syncthreads();

        {
            float mx = -3.0e38f;
#pragma unroll
            for (int j = 0; j < 16; j++) mx = fmaxf(mx, sc_s[n_l * 16 + j]);
            float sum = 0.f;
#pragma unroll
            for (int j = 0; j < 16; j++) sum += __expf(sc_s[n_l * 16 + j] - mx);
            w_s[n_l * 16 + hc_l] = __expf(sc_s[n_l * 16 + hc_l] - mx) / sum;
        }
        __syncthreads();

        float hnv;
        {
            long xb = ((long)(t * Nn + n)) * H4 + hcol;
            float a0 = __ldg(&g_xpr[xb]);
            float a1 = __ldg(&g_xpr[xb + 512]);
            float a2 = __ldg(&g_xpr[xb + 1024]);
            float a3 = __ldg(&g_xpr[xb + 1536]);
#pragma unroll
            for (int p = 0; p < PP; p++) {
                float wv = w_s[n_l * 16 + p];
                const float* awb = g_AW + ((long)(n * PP) + p) * H4 + hcol;
                a0 += wv * __ldg(awb);
                a1 += wv * __ldg(awb + 512);
                a2 += wv * __ldg(awb + 1024);
                a3 += wv * __ldg(awb + 1536);
            }
            const float4* hr4 = (const float4*)(h_s + n_l * HH);
            const float4* wr = Whs4 + hc_l;
#pragma unroll 4
            for (int k4 = 0; k4 < 128; k4++) {
                float4 hv = hr4[k4];
                float4 w0 = wr[(k4 * 4 + 0) * 16];
                float4 w1 = wr[(k4 * 4 + 1) * 16];
                float4 w2 = wr[(k4 * 4 + 2) * 16];
                float4 w3 = wr[(k4 * 4 + 3) * 16];
                a0 += hv.x*w0.x + hv.y*w1.x + hv.z*w2.x + hv.w*w3.x;
                a1 += hv.x*w0.y + hv.y*w1.y + hv.z*w2.y + hv.w*w3.y;
                a2 += hv.x*w0.z + hv.y*w1.z + hv.z*w2.z + hv.w*w3.z;
                a3 += hv.x*w0.w + hv.y*w1.w + hv.z*w2.w + hv.w*w3.w;
            }
            float ii = 1.f / (1.f + __expf(-a0));
            float ff = 1.f / (1.f + __expf(-a1));
            float oo = 1.f / (1.f + __expf(-a2));
            float gg = tanhf(a3);
            c_reg = ff * c_reg + ii * gg;
            hnv = oo * tanhf(c_reg);
            __stcg(&g_h[(t + 1) & 1][(long)n * HH + hcol], hnv);
            // fused fp16 quantize of hn (single hi plane; vocab GEMM is 1-pass)
            long hi = ((long)n * Tt + t) * HH + hcol;
            __stcg(&g_hnH[hi], __float2half_rn(hnv));
        }

        __syncthreads();
        hn_s[n_l * 16 + hc_l] = hnv;
        __syncthreads();
        if (t + 1 < Tt) {
            const float* ap = g_Ap + ((long)n * PP + hc_l) * HH + hcg * 16;
            float s = 0.f;
#pragma unroll
            for (int j = 0; j < 16; j++) s += __ldg(&ap[j]) * hn_s[n_l * 16 + j];
            __stcg(&g_scp[(t + 1) & 1][hcg][n][hc_l], s);
        }
    }
}

// ---- transpose W_vocab: [k][n] f32 -> [n][k] half (hi plane only) ----
__global__ void __launch_bounds__(256) k_trans_wv(const float* __restrict__ Wv)
{
    __shared__ float t[32][33];
    int n0 = blockIdx.x * 32, k0 = blockIdx.y * 32;
    int tx = threadIdx.x & 31, ty = threadIdx.x >> 5;
#pragma unroll
    for (int j = 0; j < 4; j++)
        t[ty + 8*j][tx] = Wv[(size_t)(k0 + ty + 8*j) * VV + n0 + tx];
    __syncthreads();
#pragma unroll
    for (int j = 0; j < 4; j++) {
        int n = n0 + ty + 8*j, k = k0 + tx;
        g_WvH[(size_t)n * HH + k] = __float2half_rn(t[tx][ty + 8*j]);
    }
}

// ================= fp16 HMMA vocab GEMM (1-pass: aH*bH) =================
// stage = A-hi 8KB | B-hi 8KB = 16KB; 4-stage pipeline = 64KB
#define VS_STG  16384
#define VS_SMEM (4 * VS_STG)

__device__ __forceinline__ uint32_t s2u(const void* p) {
    uint32_t a;
    asm("{ .reg .u64 t; cvta.to.shared.u64 t, %1; cvt.u32.u64 %0, t; }" : "=r"(a) : "l"(p));
    return a;
}

#define CPA(dst, src) asm volatile("cp.async.cg.shared.global [%0], [%1], 16;" \
    :: "r"(dst), "l"(src) : "memory")
#define LDSM4(r, addr) asm volatile( \
    "ldmatrix.sync.aligned.m8n8.x4.shared.b16 {%0,%1,%2,%3}, [%4];" \
    : "=r"((r)[0]),"=r"((r)[1]),"=r"((r)[2]),"=r"((r)[3]) : "r"(addr))
#define MMA16816(c, a, b0, b1) asm volatile( \
    "mma.sync.aligned.m16n8k16.row.col.f32.f16.f16.f32 " \
    "{%0,%1,%2,%3}, {%4,%5,%6,%7}, {%8,%9}, {%0,%1,%2,%3};" \
    : "+f"((c)[0]), "+f"((c)[1]), "+f"((c)[2]), "+f"((c)[3]) \
    : "r"((a)[0]),"r"((a)[1]),"r"((a)[2]),"r"((a)[3]), "r"(b0),"r"(b1))

__global__ void __launch_bounds__(256, 2) k_vocab_mma(const float* __restrict__ bv,
                                                      float* __restrict__ out)
{
    extern __shared__ char sm[];
    const uint32_t sbase = s2u(sm);
    const int tid = threadIdx.x;
    const int lane = tid & 31, w = tid >> 5;
    const int m0 = blockIdx.x * 128, n0 = blockIdx.y * 128;
    const int wm = (w & 1) * 64, wn = (w >> 1) * 32;

    float acc[4][4][4];
#pragma unroll
    for (int i = 0; i < 4; i++)
#pragma unroll
        for (int j = 0; j < 4; j++)
#pragma unroll
            for (int q = 0; q < 4; q++) acc[i][j][q] = 0.f;

    const int r = tid >> 1, kk = tid & 1;
    const uint32_t swo = (uint32_t)(r * 32 + ((kk ^ ((r >> 2) & 1)) << 4));
    const __half* gAH = g_hnH + (size_t)(m0 + r) * HH + kk * 8;
    const __half* gBH = g_WvH + (size_t)(n0 + r) * HH + kk * 8;

    uint32_t aoff[4], boff[2];
#pragma unroll
    for (int mt = 0; mt < 4; mt++) {
        int ml = wm + mt * 16 + (lane & 15);
        int kl = lane >> 4;
        aoff[mt] = (uint32_t)(ml * 32 + ((kl ^ ((ml >> 2) & 1)) << 4));
    }
#pragma unroll
    for (int q = 0; q < 2; q++) {
        int g = lane >> 3;
        int nl = wn + q * 16 + ((g >> 1) * 8) + (lane & 7);
        int kl = g & 1;
        boff[q] = (uint32_t)(nl * 32 + ((kl ^ ((nl >> 2) & 1)) << 4));
    }

#define VS_ISSUE(ks) do {                                                     \
    uint32_t st = sbase + (uint32_t)((ks) % 4) * VS_STG;                      \
    int kof = (ks) * 32;                                                      \
    CPA(st +    0 + swo, gAH + kof);  CPA(st +  4096 + swo, gAH + kof + 16);  \
    CPA(st + 8192 + swo, gBH + kof);  CPA(st + 12288 + swo, gBH + kof + 16);  \
    asm volatile("cp.async.commit_group;" ::: "memory");                      \
} while (0)

    VS_ISSUE(0); VS_ISSUE(1); VS_ISSUE(2);

    for (int ks = 0; ks < 16; ks++) {
        asm volatile("cp.async.wait_group 2;" ::: "memory");
        __syncthreads();
        uint32_t stb = sbase + (uint32_t)(ks % 4) * VS_STG;
#pragma unroll
        for (int s = 0; s < 2; s++) {
            uint32_t sub = stb + (uint32_t)s * 4096u;
            uint32_t aH[4][4], bH[2][4];
#pragma unroll
            for (int mt = 0; mt < 4; mt++)
                LDSM4(aH[mt], sub + aoff[mt]);
#pragma unroll
            for (int q = 0; q < 2; q++)
                LDSM4(bH[q], sub + 8192 + boff[q]);
#pragma unroll
            for (int mt = 0; mt < 4; mt++)
#pragma unroll
                for (int nt = 0; nt < 4; nt++) {
                    uint32_t b0h = bH[nt >> 1][(nt & 1) * 2];
                    uint32_t b1h = bH[nt >> 1][(nt & 1) * 2 + 1];
                    MMA16816(acc[mt][nt], aH[mt], b0h, b1h);
                }
        }
        __syncthreads();
        if (ks + 3 < 16) VS_ISSUE(ks + 3);
    }

#pragma unroll
    for (int mt = 0; mt < 4; mt++)
#pragma unroll
        for (int nt = 0; nt < 4; nt++) {
            int mrow = m0 + wm + mt * 16 + (lane >> 2);
            int ncol = n0 + wn + nt * 8 + 2 * (lane & 3);
            float b0 = __ldg(bv + ncol), b1 = __ldg(bv + ncol + 1);
            float2 v0 = make_float2(acc[mt][nt][0] + b0, acc[mt][nt][1] + b1);
            float2 v1 = make_float2(acc[mt][nt][2] + b0, acc[mt][nt][3] + b1);
            *(float2*)(out + (size_t)mrow * VV + ncol)       = v0;
            *(float2*)(out + (size_t)(mrow + 8) * VV + ncol) = v1;
        }
}

extern "C" void kernel_launch(void* const* d_in, const int* in_sizes, int n_in,
                              void* d_out, int out_size)
{
    const float* A      = (const float*)d_in[0];
    const int*   caps   = (const int*)  d_in[1];
    const float* conv_w = (const float*)d_in[2];
    const float* conv_b = (const float*)d_in[3];
    const float* Wx     = (const float*)d_in[4];
    const float* Wh     = (const float*)d_in[5];
    const float* Wattn  = (const float*)d_in[6];
    const float* b      = (const float*)d_in[7];
    const float* Wemb   = (const float*)d_in[8];
    const float* Wv     = (const float*)d_in[9];
    const float* bv     = (const float*)d_in[10];
    float* out = (float*)d_out;

    cudaFuncSetAttribute(k_vocab_mma, cudaFuncAttributeMaxDynamicSharedMemorySize, VS_SMEM);
    cudaFuncSetAttribute(k3_lstm,     cudaFuncAttributeMaxDynamicSharedMemorySize, LS_SMEM);

    k_trans_wv<<<dim3(1000, 16), 256>>>(Wv);
    k1_conv<<<dim3(8, 16), 256>>>(A, conv_w, conv_b);
    k1b_h0<<<64, 128>>>();
    k_whr<<<1024, 256>>>(Wh);
    k_gemm_aw<<<dim3(16, 8), 256>>>(Wattn);
    k_gemm_x<<<dim3(16, 16), 256>>>(Wemb, Wx, b, caps);
    k_reset<<<1, 1>>>();
    k3_lstm<<<128, 256, LS_SMEM>>>();
    k_vocab_mma<<<dim3(16, 250), 256, VS_SMEM>>>(bv, out);
}

// round 10
// speedup vs baseline: 3.4405x; 1.0215x over previous
#include <cuda_runtime.h>
#include <cuda_bf16.h>
#include <cuda_fp16.h>
#include <math.h>
#include <cstdint>

#define Nn   64
#define Tt   32
#define DA   1280
#define PP   16
#define WDIM 300
#define HH   512
#define H4   2048
#define VV   32000

__device__ float    g_Ap [Nn*PP*HH];
__device__ float    g_AW [Nn*PP*H4];
__device__ float    g_Whr[HH*H4];
__device__ float    g_xpr[(Nn*Tt)*H4];
__device__ float    g_h  [2][Nn*HH];
__device__ float    g_scp[2][32][Nn][PP];
__device__ unsigned g_bar;
__device__ __half   g_hnH[(Nn*Tt)*HH];
__device__ __half   g_WvH[(size_t)VV*HH];

// ---- K1: A_proj[r=n*16+p][h] = sum_c A[n][c][p]*conv_w[h][c] + conv_b[h] ----
__global__ void __launch_bounds__(256) k1_conv(const float* __restrict__ A,
                                               const float* __restrict__ Wc,
                                               const float* __restrict__ bc)
{
    __shared__ float As[16][68];
    __shared__ float Ws[16][68];
    int tid = threadIdx.x;
    int m0 = blockIdx.y * 64, h0 = blockIdx.x * 64;
    int tm = (tid >> 4) * 4, tn = (tid & 15) * 4;
    float acc[4][4] = {};
    int mL = tid & 63, kA = tid >> 6;
    int kW = tid & 15, hW = tid >> 4;
    int nA = (m0 + mL) >> 4, pA = (m0 + mL) & 15;
    const float* Abase = A + (long)nA * (DA * PP) + pA;
    for (int c0 = 0; c0 < DA; c0 += 16) {
#pragma unroll
        for (int it = 0; it < 4; it++) {
            int k = kA + it * 4;
            As[k][mL] = Abase[(c0 + k) * PP];
        }
#pragma unroll
        for (int it = 0; it < 4; it++) {
            int h = hW + it * 16;
            Ws[kW][h] = Wc[(long)(h0 + h) * DA + c0 + kW];
        }
        __syncthreads();
#pragma unroll
        for (int k = 0; k < 16; k++) {
            float4 a = *(const float4*)&As[k][tm];
            float4 b = *(const float4*)&Ws[k][tn];
            float av[4] = {a.x,a.y,a.z,a.w};
            float bv[4] = {b.x,b.y,b.z,b.w};
#pragma unroll
            for (int i = 0; i < 4; i++)
#pragma unroll
                for (int j = 0; j < 4; j++) acc[i][j] += av[i] * bv[j];
        }
        __syncthreads();
    }
#pragma unroll
    for (int i = 0; i < 4; i++) {
        int r = m0 + tm + i;
#pragma unroll
        for (int j = 0; j < 4; j++)
            g_Ap[(long)r * HH + h0 + tn + j] = acc[i][j] + bc[h0 + tn + j];
    }
}

// ---- h0 = mean over 16 spatial positions ----
__global__ void k1b_h0()
{
    int n = blockIdx.x, t = threadIdx.x;
    const float4* ap = (const float4*)(g_Ap + (long)n * PP * HH);
    float4 s = make_float4(0.f,0.f,0.f,0.f);
#pragma unroll
    for (int p = 0; p < PP; p++) {
        float4 v = ap[p * 128 + t];
        s.x += v.x; s.y += v.y; s.z += v.z; s.w += v.w;
    }
    s.x *= 0.0625f; s.y *= 0.0625f; s.z *= 0.0625f; s.w *= 0.0625f;
    ((float4*)(g_h[0] + (long)n * HH))[t] = s;
}

// ---- gate-interleave Wh ----
__global__ void k_whr(const float* __restrict__ Wh)
{
    int idx = blockIdx.x * 256 + threadIdx.x;
    int k = idx >> 9, h = idx & 511;
    const float* src = Wh + (long)k * H4 + h;
    ((float4*)g_Whr)[idx] = make_float4(src[0], src[512], src[1024], src[1536]);
}

// ---- generic 128x128 SGEMM body (AW and X pre-GEMMs) ----
template<bool GATHER, bool BIAS>
__device__ __forceinline__ void gemm128_body(
    const float* __restrict__ Amat, int lda, int Kd,
    const float* __restrict__ Bmat, int ldb,
    const float* __restrict__ bias,
    float* __restrict__ C, int ldc,
    const int* __restrict__ caps)
{
    __shared__ float As[16][132];
    __shared__ float Bs[16][128];
    int tid = threadIdx.x;
    int m0 = blockIdx.y * 128, c0 = blockIdx.x * 128;
    int tm = (tid >> 4) * 8, tn = (tid & 15) * 8;
    float acc[8][8] = {};
    int mA = tid >> 2, kq = (tid & 3) * 4;
    const float *arow0, *arow1;
    {
        int r0 = m0 + mA, r1 = r0 + 64;
        if (GATHER) {
            arow0 = Amat + (long)caps[(r0 & 63) * Tt + (r0 >> 6)] * lda;
            arow1 = Amat + (long)caps[(r1 & 63) * Tt + (r1 >> 6)] * lda;
        } else {
            arow0 = Amat + (long)r0 * lda;
            arow1 = Amat + (long)r1 * lda;
        }
    }
    int kB = tid >> 5, cB = (tid & 31) * 4;
    int nchunk = (Kd + 15) >> 4;
    for (int ch = 0; ch < nchunk; ch++) {
        int k0 = ch * 16;
        if (k0 + 16 <= Kd) {
            float4 a0 = *(const float4*)(arow0 + k0 + kq);
            float4 a1 = *(const float4*)(arow1 + k0 + kq);
            As[kq+0][mA] = a0.x; As[kq+1][mA] = a0.y;
            As[kq+2][mA] = a0.z; As[kq+3][mA] = a0.w;
            As[kq+0][mA+64] = a1.x; As[kq+1][mA+64] = a1.y;
            As[kq+2][mA+64] = a1.z; As[kq+3][mA+64] = a1.w;
        } else {
#pragma unroll
            for (int i = 0; i < 4; i++) {
                int k = k0 + kq + i;
                As[kq+i][mA]    = (k < Kd) ? arow0[k] : 0.f;
                As[kq+i][mA+64] = (k < Kd) ? arow1[k] : 0.f;
            }
        }
#pragma unroll
        for (int it = 0; it < 2; it++) {
            int k = k0 + kB + it * 8;
            float4 bv = (k < Kd) ? *(const float4*)(Bmat + (long)k * ldb + c0 + cB)
                                 : make_float4(0.f,0.f,0.f,0.f);
            *(float4*)&Bs[kB + it*8][cB] = bv;
        }
        __syncthreads();
#pragma unroll
        for (int k = 0; k < 16; k++) {
            float4 a0 = *(const float4*)&As[k][tm];
            float4 a1 = *(const float4*)&As[k][tm+4];
            float4 b0 = *(const float4*)&Bs[k][tn];
            float4 b1 = *(const float4*)&Bs[k][tn+4];
            float av[8] = {a0.x,a0.y,a0.z,a0.w,a1.x,a1.y,a1.z,a1.w};
            float bv[8] = {b0.x,b0.y,b0.z,b0.w,b1.x,b1.y,b1.z,b1.w};
#pragma unroll
            for (int i = 0; i < 8; i++)
#pragma unroll
                for (int j = 0; j < 8; j++) acc[i][j] += av[i] * bv[j];
        }
        __syncthreads();
    }
    float4 bia0 = make_float4(0,0,0,0), bia1 = bia0;
    if (BIAS) {
        bia0 = *(const float4*)(bias + c0 + tn);
        bia1 = *(const float4*)(bias + c0 + tn + 4);
    }
#pragma unroll
    for (int i = 0; i < 8; i++) {
        long r = m0 + tm + i;
        float4 o0 = make_float4(acc[i][0]+bia0.x, acc[i][1]+bia0.y,
                                acc[i][2]+bia0.z, acc[i][3]+bia0.w);
        float4 o1 = make_float4(acc[i][4]+bia1.x, acc[i][5]+bia1.y,
                                acc[i][6]+bia1.z, acc[i][7]+bia1.w);
        *(float4*)(C + r * ldc + c0 + tn)     = o0;
        *(float4*)(C + r * ldc + c0 + tn + 4) = o1;
    }
}

__global__ void __launch_bounds__(256, 2) k_gemm_aw(const float* __restrict__ Wattn)
{ gemm128_body<false,false>(g_Ap, HH, HH, Wattn, H4, nullptr, g_AW, H4, nullptr); }

__global__ void __launch_bounds__(256, 2) k_gemm_x(const float* __restrict__ Wemb,
                                                   const float* __restrict__ Wx,
                                                   const float* __restrict__ bb,
                                                   const int*   __restrict__ caps)
{ gemm128_body<true,true>(Wemb, WDIM, WDIM, Wx, H4, bb, g_xpr, H4, caps); }

__global__ void k_reset() { g_bar = 0u; }

// ================= persistent attention-LSTM (SMEM-resident Wh) =================
#define LS_SMEM 166912

__global__ void __launch_bounds__(256) k3_lstm()
{
    extern __shared__ char sm[];
    float4* Whs4 = (float4*)sm;                    // [512][16] float4 = 128KB
    float*  h_s  = (float*)(sm + 131072);          // [16][512]        = 32KB
    float*  sc_s = (float*)(sm + 163840);
    float*  w_s  = (float*)(sm + 164864);
    float*  hn_s = (float*)(sm + 165888);

    const int tid = threadIdx.x, blk = blockIdx.x;
    const int ng = blk >> 5, hcg = blk & 31;
    const int n0 = ng * 16;
    const int n_l = tid >> 4, hc_l = tid & 15;
    const int n = n0 + n_l;
    const int hcol = hcg * 16 + hc_l;
    const float SCALE = 0.04419417382415922f;  // 1/sqrt(512)

    for (int i = tid; i < 8192; i += 256) {
        int k = i >> 4, hc = i & 15;
        Whs4[i] = ((const float4*)g_Whr)[k * 512 + hcg * 16 + hc];
    }
    float c_reg = g_h[0][(long)n * HH + hcol];

    hn_s[n_l * 16 + hc_l] = c_reg;
    __syncthreads();
    {
        const float* ap = g_Ap + ((long)n * PP + hc_l) * HH + hcg * 16;
        float s = 0.f;
#pragma unroll
        for (int j = 0; j < 16; j++) s += __ldg(&ap[j]) * hn_s[n_l * 16 + j];
        __stcg(&g_scp[0][hcg][n][hc_l], s);
    }

    for (int t = 0; t < Tt; t++) {
        // grid barrier
        __threadfence();
        __syncthreads();
        if (tid == 0) {
            atomicAdd(&g_bar, 1u);
            unsigned target = (unsigned)(t + 1) * 128u;
            while (*(volatile unsigned*)&g_bar < target) { }
        }
        __syncthreads();

        const float4* hg = (const float4*)(g_h[t & 1] + (long)n0 * HH);
        float4* hs4 = (float4*)h_s;
#pragma unroll
        for (int q = 0; q < 8; q++)
            hs4[tid + q * 256] = __ldcg(&hg[tid + q * 256]);

        {
            const float* sp = &g_scp[t & 1][0][n][hc_l];
            float s = 0.f;
#pragma unroll
            for (int j = 0; j < 32; j++) s += __ldcg(sp + j * (Nn * PP));
            sc_s[n_l * 16 + hc_l] = s * SCALE;
        }
        __syncthreads();

        {
            float mx = -3.0e38f;
#pragma unroll
            for (int j = 0; j < 16; j++) mx = fmaxf(mx, sc_s[n_l * 16 + j]);
            float sum = 0.f;
#pragma unroll
            for (int j = 0; j < 16; j++) sum += __expf(sc_s[n_l * 16 + j] - mx);
            w_s[n_l * 16 + hc_l] = __expf(sc_s[n_l * 16 + hc_l] - mx) / sum;
        }
        __syncthreads();

        float hnv;
        {
            long xb = ((long)(t * Nn + n)) * H4 + hcol;
            float a0 = __ldg(&g_xpr[xb]);
            float a1 = __ldg(&g_xpr[xb + 512]);
            float a2 = __ldg(&g_xpr[xb + 1024]);
            float a3 = __ldg(&g_xpr[xb + 1536]);
#pragma unroll
            for (int p = 0; p < PP; p++) {
                float wv = w_s[n_l * 16 + p];
                const float* awb = g_AW + ((long)(n * PP) + p) * H4 + hcol;
                a0 += wv * __ldg(awb);
                a1 += wv * __ldg(awb + 512);
                a2 += wv * __ldg(awb + 1024);
                a3 += wv * __ldg(awb + 1536);
            }
            const float4* hr4 = (const float4*)(h_s + n_l * HH);
            const float4* wr = Whs4 + hc_l;
#pragma unroll 4
            for (int k4 = 0; k4 < 128; k4++) {
                float4 hv = hr4[k4];
                float4 w0 = wr[(k4 * 4 + 0) * 16];
                float4 w1 = wr[(k4 * 4 + 1) * 16];
                float4 w2 = wr[(k4 * 4 + 2) * 16];
                float4 w3 = wr[(k4 * 4 + 3) * 16];
                a0 += hv.x*w0.x + hv.y*w1.x + hv.z*w2.x + hv.w*w3.x;
                a1 += hv.x*w0.y + hv.y*w1.y + hv.z*w2.y + hv.w*w3.y;
                a2 += hv.x*w0.z + hv.y*w1.z + hv.z*w2.z + hv.w*w3.z;
                a3 += hv.x*w0.w + hv.y*w1.w + hv.z*w2.w + hv.w*w3.w;
            }
            float ii = 1.f / (1.f + __expf(-a0));
            float ff = 1.f / (1.f + __expf(-a1));
            float oo = 1.f / (1.f + __expf(-a2));
            float gg = tanhf(a3);
            c_reg = ff * c_reg + ii * gg;
            hnv = oo * tanhf(c_reg);
            __stcg(&g_h[(t + 1) & 1][(long)n * HH + hcol], hnv);
            // fused fp16 quantize of hn (single hi plane; vocab GEMM is 1-pass)
            long hi = ((long)n * Tt + t) * HH + hcol;
            __stcg(&g_hnH[hi], __float2half_rn(hnv));
        }

        __syncthreads();
        hn_s[n_l * 16 + hc_l] = hnv;
        __syncthreads();
        if (t + 1 < Tt) {
            const float* ap = g_Ap + ((long)n * PP + hc_l) * HH + hcg * 16;
            float s = 0.f;
#pragma unroll
            for (int j = 0; j < 16; j++) s += __ldg(&ap[j]) * hn_s[n_l * 16 + j];
            __stcg(&g_scp[(t + 1) & 1][hcg][n][hc_l], s);
        }
    }
}

// ---- transpose W_vocab: [k][n] f32 -> [n][k] half (hi plane only) ----
__global__ void __launch_bounds__(256) k_trans_wv(const float* __restrict__ Wv)
{
    __shared__ float t[32][33];
    int n0 = blockIdx.x * 32, k0 = blockIdx.y * 32;
    int tx = threadIdx.x & 31, ty = threadIdx.x >> 5;
#pragma unroll
    for (int j = 0; j < 4; j++)
        t[ty + 8*j][tx] = Wv[(size_t)(k0 + ty + 8*j) * VV + n0 + tx];
    __syncthreads();
#pragma unroll
    for (int j = 0; j < 4; j++) {
        int n = n0 + ty + 8*j, k = k0 + tx;
        g_WvH[(size_t)n * HH + k] = __float2half_rn(t[tx][ty + 8*j]);
    }
}

// ================= fp16 HMMA vocab GEMM (1-pass: aH*bH) =================
// stage = A-hi 8KB | B-hi 8KB = 16KB; 4-stage pipeline = 64KB
#define VS_STG  16384
#define VS_SMEM (4 * VS_STG)

__device__ __forceinline__ uint32_t s2u(const void* p) {
    uint32_t a;
    asm("{ .reg .u64 t; cvta.to.shared.u64 t, %1; cvt.u32.u64 %0, t; }" : "=r"(a) : "l"(p));
    return a;
}

#define CPA(dst, src) asm volatile("cp.async.cg.shared.global [%0], [%1], 16;" \
    :: "r"(dst), "l"(src) : "memory")
#define LDSM4(r, addr) asm volatile( \
    "ldmatrix.sync.aligned.m8n8.x4.shared.b16 {%0,%1,%2,%3}, [%4];" \
    : "=r"((r)[0]),"=r"((r)[1]),"=r"((r)[2]),"=r"((r)[3]) : "r"(addr))
#define MMA16816(c, a, b0, b1) asm volatile( \
    "mma.sync.aligned.m16n8k16.row.col.f32.f16.f16.f32 " \
    "{%0,%1,%2,%3}, {%4,%5,%6,%7}, {%8,%9}, {%0,%1,%2,%3};" \
    : "+f"((c)[0]), "+f"((c)[1]), "+f"((c)[2]), "+f"((c)[3]) \
    : "r"((a)[0]),"r"((a)[1]),"r"((a)[2]),"r"((a)[3]), "r"(b0),"r"(b1))

__global__ void __launch_bounds__(256, 2) k_vocab_mma(const float* __restrict__ bv,
                                                      float* __restrict__ out)
{
    extern __shared__ char sm[];
    const uint32_t sbase = s2u(sm);
    const int tid = threadIdx.x;
    const int lane = tid & 31, w = tid >> 5;
    const int m0 = blockIdx.x * 128, n0 = blockIdx.y * 128;
    const int wm = (w & 1) * 64, wn = (w >> 1) * 32;

    float acc[4][4][4];
#pragma unroll
    for (int i = 0; i < 4; i++)
#pragma unroll
        for (int j = 0; j < 4; j++)
#pragma unroll
            for (int q = 0; q < 4; q++) acc[i][j][q] = 0.f;

    const int r = tid >> 1, kk = tid & 1;
    const uint32_t swo = (uint32_t)(r * 32 + ((kk ^ ((r >> 2) & 1)) << 4));
    const __half* gAH = g_hnH + (size_t)(m0 + r) * HH + kk * 8;
    const __half* gBH = g_WvH + (size_t)(n0 + r) * HH + kk * 8;

    uint32_t aoff[4], boff[2];
#pragma unroll
    for (int mt = 0; mt < 4; mt++) {
        int ml = wm + mt * 16 + (lane & 15);
        int kl = lane >> 4;
        aoff[mt] = (uint32_t)(ml * 32 + ((kl ^ ((ml >> 2) & 1)) << 4));
    }
#pragma unroll
    for (int q = 0; q < 2; q++) {
        int g = lane >> 3;
        int nl = wn + q * 16 + ((g >> 1) * 8) + (lane & 7);
        int kl = g & 1;
        boff[q] = (uint32_t)(nl * 32 + ((kl ^ ((nl >> 2) & 1)) << 4));
    }

#define VS_ISSUE(ks) do {                                                     \
    uint32_t st = sbase + (uint32_t)((ks) % 4) * VS_STG;                      \
    int kof = (ks) * 32;                                                      \
    CPA(st +    0 + swo, gAH + kof);  CPA(st +  4096 + swo, gAH + kof + 16);  \
    CPA(st + 8192 + swo, gBH + kof);  CPA(st + 12288 + swo, gBH + kof + 16);  \
    asm volatile("cp.async.commit_group;" ::: "memory");                      \
} while (0)

    VS_ISSUE(0); VS_ISSUE(1); VS_ISSUE(2);

    for (int ks = 0; ks < 16; ks++) {
        asm volatile("cp.async.wait_group 2;" ::: "memory");
        __syncthreads();
        uint32_t stb = sbase + (uint32_t)(ks % 4) * VS_STG;
#pragma unroll
        for (int s = 0; s < 2; s++) {
            uint32_t sub = stb + (uint32_t)s * 4096u;
            uint32_t aH[4][4], bH[2][4];
#pragma unroll
            for (int mt = 0; mt < 4; mt++)
                LDSM4(aH[mt], sub + aoff[mt]);
#pragma unroll
            for (int q = 0; q < 2; q++)
                LDSM4(bH[q], sub + 8192 + boff[q]);
#pragma unroll
            for (int mt = 0; mt < 4; mt++)
#pragma unroll
                for (int nt = 0; nt < 4; nt++) {
                    uint32_t b0h = bH[nt >> 1][(nt & 1) * 2];
                    uint32_t b1h = bH[nt >> 1][(nt & 1) * 2 + 1];
                    MMA16816(acc[mt][nt], aH[mt], b0h, b1h);
                }
        }
        __syncthreads();
        if (ks + 3 < 16) VS_ISSUE(ks + 3);
    }

#pragma unroll
    for (int mt = 0; mt < 4; mt++)
#pragma unroll
        for (int nt = 0; nt < 4; nt++) {
            int mrow = m0 + wm + mt * 16 + (lane >> 2);
            int ncol = n0 + wn + nt * 8 + 2 * (lane & 3);
            float b0 = __ldg(bv + ncol), b1 = __ldg(bv + ncol + 1);
            float2 v0 = make_float2(acc[mt][nt][0] + b0, acc[mt][nt][1] + b1);
            float2 v1 = make_float2(acc[mt][nt][2] + b0, acc[mt][nt][3] + b1);
            *(float2*)(out + (size_t)mrow * VV + ncol)       = v0;
            *(float2*)(out + (size_t)(mrow + 8) * VV + ncol) = v1;
        }
}

extern "C" void kernel_launch(void* const* d_in, const int* in_sizes, int n_in,
                              void* d_out, int out_size)
{
    const float* A      = (const float*)d_in[0];
    const int*   caps   = (const int*)  d_in[1];
    const float* conv_w = (const float*)d_in[2];
    const float* conv_b = (const float*)d_in[3];
    const float* Wx     = (const float*)d_in[4];
    const float* Wh     = (const float*)d_in[5];
    const float* Wattn  = (const float*)d_in[6];
    const float* b      = (const float*)d_in[7];
    const float* Wemb   = (const float*)d_in[8];
    const float* Wv     = (const float*)d_in[9];
    const float* bv     = (const float*)d_in[10];
    float* out = (float*)d_out;

    cudaFuncSetAttribute(k_vocab_mma, cudaFuncAttributeMaxDynamicSharedMemorySize, VS_SMEM);
    cudaFuncSetAttribute(k3_lstm,     cudaFuncAttributeMaxDynamicSharedMemorySize, LS_SMEM);

    k_trans_wv<<<dim3(1000, 16), 256>>>(Wv);
    k1_conv<<<dim3(8, 16), 256>>>(A, conv_w, conv_b);
    k1b_h0<<<64, 128>>>();
    k_whr<<<1024, 256>>>(Wh);
    k_gemm_aw<<<dim3(16, 8), 256>>>(Wattn);
    k_gemm_x<<<dim3(16, 16), 256>>>(Wemb, Wx, b, caps);
    k_reset<<<1, 1>>>();
    k3_lstm<<<128, 256, LS_SMEM>>>();
    k_vocab_mma<<<dim3(16, 250), 256, VS_SMEM>>>(bv, out);
}